// round 8
// baseline (speedup 1.0000x reference)
#include <cuda_runtime.h>
#include <math.h>

#define NN 4096
#define NPTS 32768

typedef unsigned long long ull;

__device__ __forceinline__ ull pack2(float v) {
    ull r; unsigned u = __float_as_uint(v);
    asm("mov.b64 %0,{%1,%1};" : "=l"(r) : "r"(u));
    return r;
}
__device__ __forceinline__ ull pack2f(float lo, float hi) {
    ull r;
    asm("mov.b64 %0,{%1,%2};" : "=l"(r) : "r"(__float_as_uint(lo)), "r"(__float_as_uint(hi)));
    return r;
}
__device__ __forceinline__ void ffma2(ull &d, ull a, ull b) {
    asm("fma.rn.f32x2 %0, %1, %2, %0;" : "+l"(d) : "l"(a), "l"(b));
}
__device__ __forceinline__ float lo2(ull v) { return __uint_as_float((unsigned)v); }
__device__ __forceinline__ float hi2(ull v) { return __uint_as_float((unsigned)(v >> 32)); }

// scratch (static __device__, no allocation)
__device__ float g_lcc[NPTS * 10];   // (pt, k, xy)
__device__ float g_lf [NPTS * 64];   // local_feats

// out layout: [cls 32768*128 | topo 32768*128 | angle 32768 | axes 32768*2]
#define OFF_TOPO 4194304
#define OFF_ANG  8388608
#define OFF_AX   8421376

// ---------------- Kernel A: KNN (reference-bit-exact dist) + slaev2 eigh + lcc ----------------
__global__ __launch_bounds__(128)
void knn_geom_kernel(const float* __restrict__ xg, float* __restrict__ out)
{
    __shared__ float2 sp[NN];
    __shared__ float  ssq[NN];
    const int b = blockIdx.y;
    const float2* xb = reinterpret_cast<const float2*>(xg) + (size_t)b * NN;
    for (int i = threadIdx.x; i < NN; i += 128) {
        float2 v = xb[i];
        sp[i] = v;
        ssq[i] = __fadd_rn(__fmul_rn(v.x, v.x), __fmul_rn(v.y, v.y));
    }
    __syncthreads();

    const int n = blockIdx.x * 128 + threadIdx.x;
    const float qx = sp[n].x, qy = sp[n].y;
    const float sqn = ssq[n];

    float d0 = 3.4e38f, d1 = 3.4e38f, d2 = 3.4e38f, d3 = 3.4e38f, d4 = 3.4e38f;
    int   i0 = 0, i1 = 0, i2 = 0, i3 = 0, i4 = 0;

    #pragma unroll 4
    for (int m = 0; m < NN; ++m) {
        float2 p = sp[m];
        float dot = __fmaf_rn(p.y, qy, __fmul_rn(p.x, qx));
        float dd = __fsub_rn(__fadd_rn(sqn, ssq[m]), __fmul_rn(2.0f, dot));
        if (dd < d4) {                      // strict <: lax.top_k stable tie-break by index
            if (dd < d3) {
                d4 = d3; i4 = i3;
                if (dd < d2) {
                    d3 = d2; i3 = i2;
                    if (dd < d1) {
                        d2 = d1; i2 = i1;
                        if (dd < d0) { d1 = d0; i1 = i0; d0 = dd; i0 = m; }
                        else          { d1 = dd; i1 = m; }
                    } else { d2 = dd; i2 = m; }
                } else { d3 = dd; i3 = m; }
            } else { d4 = dd; i4 = m; }
        }
    }

    int nb[5] = {i0, i1, i2, i3, i4};
    float rx[5], ry[5];
    #pragma unroll
    for (int k = 0; k < 5; ++k) {
        float2 p = sp[nb[k]];
        rx[k] = __fsub_rn(p.x, qx);
        ry[k] = __fsub_rn(p.y, qy);
    }
    float sxs = __fadd_rn(__fadd_rn(__fadd_rn(__fadd_rn(rx[0], rx[1]), rx[2]), rx[3]), rx[4]);
    float sys = __fadd_rn(__fadd_rn(__fadd_rn(__fadd_rn(ry[0], ry[1]), ry[2]), ry[3]), ry[4]);
    float mx = __fdiv_rn(sxs, 5.0f);
    float my = __fdiv_rn(sys, 5.0f);
    float cx[5], cy[5];
    float sxx = 0.f, sxy = 0.f, syy = 0.f;
    #pragma unroll
    for (int k = 0; k < 5; ++k) {
        cx[k] = __fsub_rn(rx[k], mx);
        cy[k] = __fsub_rn(ry[k], my);
        sxx = __fmaf_rn(cx[k], cx[k], sxx);
        sxy = __fmaf_rn(cx[k], cy[k], sxy);
        syy = __fmaf_rn(cy[k], cy[k], syy);
    }
    float a  = __fadd_rn(__fmul_rn(sxx, 0.25f), 1e-6f);
    float bv = __fmul_rn(sxy, 0.25f);
    float c  = __fadd_rn(__fmul_rn(syy, 0.25f), 1e-6f);

    // ---- LAPACK slaev2 (a,c > 0 => sm > 0 => sgn1 = +1) ----
    float smv = a + c, df = a - c;
    float adf = fabsf(df);
    float tb  = bv + bv;
    float ab  = fabsf(tb);
    float rt;
    if (adf > ab)      { float t = ab / adf; rt = adf * sqrtf(1.f + t*t); }
    else if (adf < ab) { float t = adf / ab; rt = ab * sqrtf(1.f + t*t); }
    else               { rt = ab * 1.4142135623730951f; }
    float rt1 = 0.5f * (smv + rt);
    float acmx, acmn;
    if (fabsf(a) > fabsf(c)) { acmx = a; acmn = c; } else { acmx = c; acmn = a; }
    float rt2 = (acmx / rt1) * acmn - (bv / rt1) * bv;
    float cs; int sgn2;
    if (df >= 0.f) { cs = df + rt; sgn2 = 1; }
    else           { cs = df - rt; sgn2 = -1; }
    float acs = fabsf(cs), cs1, sn1;
    if (acs > ab)       { float ct = -tb / cs; sn1 = 1.f / sqrtf(1.f + ct*ct); cs1 = ct * sn1; }
    else if (ab == 0.f) { cs1 = 1.f; sn1 = 0.f; }
    else                { float tn = -cs / tb; cs1 = 1.f / sqrtf(1.f + tn*tn); sn1 = tn * cs1; }
    if (sgn2 == 1)      { float t = cs1; cs1 = -sn1; sn1 = t; }

    float e0, e1, v00, v10, v01, v11;
    if (rt2 < rt1) { e0 = rt2; e1 = rt1; v00 = -sn1; v10 = cs1; v01 = cs1;  v11 = sn1; }
    else           { e0 = rt1; e1 = rt2; v00 = cs1;  v10 = sn1; v01 = -sn1; v11 = cs1; }

    const int pt = b * NN + n;
    out[OFF_ANG + pt] = atan2f(v11, v01);
    float sL = sqrtf(fmaxf(e1, 1e-6f));
    float sS = sqrtf(fmaxf(e0, 1e-6f));
    float den = fmaxf(sL, sS) + 1e-6f;
    out[OFF_AX + pt * 2 + 0] = fmaxf(sL / den, 0.2f);
    out[OFF_AX + pt * 2 + 1] = fmaxf(sS / den, 0.2f);

    float* lp = g_lcc + (size_t)pt * 10;
    #pragma unroll
    for (int k = 0; k < 5; ++k) {
        lp[2*k]   = __fmaf_rn(cy[k], v10, __fmul_rn(cx[k], v00));
        lp[2*k+1] = __fmaf_rn(cy[k], v11, __fmul_rn(cx[k], v01));
    }
}

// ---------------- Kernel B: local MLP 2->64->128->64 + max over K (f32x2) ----------------
// 32 points/CTA (160 k-rows), 256 threads.
#define B_SMEM_FLOATS (128 + 64 + 8192 + 128 + 8192 + 64 + 320 + 64*161 + 160*130)
__global__ __launch_bounds__(256)
void local_mlp_kernel(const float* __restrict__ lw1, const float* __restrict__ lb1,
                      const float* __restrict__ lw2, const float* __restrict__ lb2,
                      const float* __restrict__ lw3, const float* __restrict__ lb3)
{
    extern __shared__ float smf[];
    float* w1s  = smf;             // 128
    float* b1s  = w1s + 128;       // 64
    float* w2s  = b1s + 64;        // 8192
    float* b2s  = w2s + 8192;      // 128
    float* w3s  = b2s + 128;       // 8192
    float* b3s  = w3s + 8192;      // 64
    float* lccs = b3s + 64;        // 320
    float* h1T  = lccs + 320;      // 64 x 161 (k-major)
    float* h2s  = h1T + 64*161;    // 160 x 130 (even stride for 64-bit st)

    const int tid  = threadIdx.x;
    const int base = blockIdx.x * 32;

    for (int i = tid; i < 128;  i += 256) { w1s[i] = lw1[i]; b2s[i] = lb2[i]; }
    for (int i = tid; i < 64;   i += 256) { b1s[i] = lb1[i]; b3s[i] = lb3[i]; }
    for (int i = tid; i < 8192; i += 256) { w2s[i] = lw2[i]; w3s[i] = lw3[i]; }
    for (int i = tid; i < 320;  i += 256) lccs[i] = g_lcc[(size_t)base * 10 + i];
    __syncthreads();

    // stage 1: h1 (160x64) -> transposed h1T[c*161 + r]
    for (int idx = tid; idx < 160 * 64; idx += 256) {
        int r = idx >> 6, c = idx & 63;
        float v = fmaf(lccs[2*r], w1s[c], fmaf(lccs[2*r+1], w1s[64 + c], b1s[c]));
        h1T[c * 161 + r] = fmaxf(v, 0.f);
    }
    __syncthreads();

    const int p  = tid >> 3;     // point 0..31
    const int cg = tid & 7;      // column pair group 0..7
    const int r0 = p * 5;
    const int c0 = 2 * cg;       // pair base: cols c0+16i, c0+16i+1

    // stage 2: h2 (160x128), 5 rows x 8 col-pairs per thread, f32x2
    ull acc[5][8];
    #pragma unroll
    for (int i = 0; i < 8; ++i) {
        ull bp = *reinterpret_cast<const ull*>(b2s + c0 + 16*i);
        #pragma unroll
        for (int j = 0; j < 5; ++j) acc[j][i] = bp;
    }
    for (int k = 0; k < 64; ++k) {
        ull av[5];
        #pragma unroll
        for (int j = 0; j < 5; ++j) av[j] = pack2(h1T[k * 161 + r0 + j]);
        ull wv[8];
        #pragma unroll
        for (int i = 0; i < 8; ++i) wv[i] = *reinterpret_cast<const ull*>(w2s + k*128 + c0 + 16*i);
        #pragma unroll
        for (int j = 0; j < 5; ++j)
            #pragma unroll
            for (int i = 0; i < 8; ++i)
                ffma2(acc[j][i], av[j], wv[i]);
    }
    #pragma unroll
    for (int j = 0; j < 5; ++j)
        #pragma unroll
        for (int i = 0; i < 8; ++i) {
            float2 v = make_float2(fmaxf(lo2(acc[j][i]), 0.f), fmaxf(hi2(acc[j][i]), 0.f));
            *reinterpret_cast<float2*>(h2s + (r0 + j) * 130 + c0 + 16*i) = v;
        }
    __syncthreads();

    // stage 3: h3 (160x64), 5 rows x 4 col-pairs, fused relu+max over K
    ull acc3[5][4];
    #pragma unroll
    for (int i = 0; i < 4; ++i) {
        ull bp = *reinterpret_cast<const ull*>(b3s + c0 + 16*i);
        #pragma unroll
        for (int j = 0; j < 5; ++j) acc3[j][i] = bp;
    }
    for (int k = 0; k < 128; ++k) {
        ull av[5];
        #pragma unroll
        for (int j = 0; j < 5; ++j) av[j] = pack2(h2s[(r0 + j) * 130 + k]);
        ull wv[4];
        #pragma unroll
        for (int i = 0; i < 4; ++i) wv[i] = *reinterpret_cast<const ull*>(w3s + k*64 + c0 + 16*i);
        #pragma unroll
        for (int j = 0; j < 5; ++j)
            #pragma unroll
            for (int i = 0; i < 4; ++i)
                ffma2(acc3[j][i], av[j], wv[i]);
    }
    #pragma unroll
    for (int i = 0; i < 4; ++i) {
        float mlo = 0.f, mhi = 0.f;   // relu floor
        #pragma unroll
        for (int j = 0; j < 5; ++j) {
            mlo = fmaxf(mlo, lo2(acc3[j][i]));
            mhi = fmaxf(mhi, hi2(acc3[j][i]));
        }
        *reinterpret_cast<float2*>(g_lf + (size_t)(base + p) * 64 + c0 + 16*i) = make_float2(mlo, mhi);
    }
}

// ---------------- Kernel C/D: heads  in -> 128 relu -> 128 relu (f32x2, P=2) ----------------
// 64 points/CTA, 256 threads: pg = tid>>3 (32), cg = tid&7; thread tile 2 rows x 8 col-pairs.
template<int INDIM, int INSTRIDE, bool USEX>
__global__ __launch_bounds__(256)
void head_kernel(const float* __restrict__ xg,
                 const float* __restrict__ w1, const float* __restrict__ b1,
                 const float* __restrict__ w2, const float* __restrict__ b2,
                 float* __restrict__ outp)
{
    extern __shared__ float smf[];
    float* w1s = smf;                   // INDIM*128
    float* b1s = w1s + INDIM * 128;     // 128
    float* w2s = b1s + 128;             // 16384
    float* b2s = w2s + 16384;           // 128
    float* ins = b2s + 128;             // 64 * INSTRIDE
    float* hs  = ins + 64 * INSTRIDE;   // 64 * 130

    const int tid  = threadIdx.x;
    const int base = blockIdx.x * 64;

    for (int i = tid; i < INDIM * 128; i += 256) w1s[i] = w1[i];
    for (int i = tid; i < 16384;       i += 256) w2s[i] = w2[i];
    for (int i = tid; i < 128;         i += 256) { b1s[i] = b1[i]; b2s[i] = b2[i]; }
    const int xoff = USEX ? 2 : 0;
    for (int idx = tid; idx < 64 * 64; idx += 256) {
        int p = idx >> 6, c = idx & 63;
        ins[p * INSTRIDE + xoff + c] = g_lf[(size_t)(base + p) * 64 + c];
    }
    if (USEX) {
        for (int idx = tid; idx < 128; idx += 256) {
            int p = idx >> 1, c = idx & 1;
            ins[p * INSTRIDE + c] = xg[(size_t)(base + p) * 2 + c];
        }
    }
    __syncthreads();

    const int p0 = (tid >> 3) * 2;   // rows p0, p0+1
    const int cg = tid & 7;
    const int c0 = 2 * cg;

    // stage 1
    ull acc[2][8];
    #pragma unroll
    for (int i = 0; i < 8; ++i) {
        ull bp = *reinterpret_cast<const ull*>(b1s + c0 + 16*i);
        acc[0][i] = bp; acc[1][i] = bp;
    }
    for (int k = 0; k < INDIM; ++k) {
        ull a0 = pack2(ins[p0 * INSTRIDE + k]);
        ull a1 = pack2(ins[(p0 + 1) * INSTRIDE + k]);
        ull wv[8];
        #pragma unroll
        for (int i = 0; i < 8; ++i) wv[i] = *reinterpret_cast<const ull*>(w1s + k*128 + c0 + 16*i);
        #pragma unroll
        for (int i = 0; i < 8; ++i) { ffma2(acc[0][i], a0, wv[i]); ffma2(acc[1][i], a1, wv[i]); }
    }
    #pragma unroll
    for (int j = 0; j < 2; ++j)
        #pragma unroll
        for (int i = 0; i < 8; ++i) {
            float2 v = make_float2(fmaxf(lo2(acc[j][i]), 0.f), fmaxf(hi2(acc[j][i]), 0.f));
            *reinterpret_cast<float2*>(hs + (p0 + j) * 130 + c0 + 16*i) = v;
        }
    __syncthreads();

    // stage 2
    ull acc2[2][8];
    #pragma unroll
    for (int i = 0; i < 8; ++i) {
        ull bp = *reinterpret_cast<const ull*>(b2s + c0 + 16*i);
        acc2[0][i] = bp; acc2[1][i] = bp;
    }
    for (int k = 0; k < 128; ++k) {
        ull a0 = pack2(hs[p0 * 130 + k]);
        ull a1 = pack2(hs[(p0 + 1) * 130 + k]);
        ull wv[8];
        #pragma unroll
        for (int i = 0; i < 8; ++i) wv[i] = *reinterpret_cast<const ull*>(w2s + k*128 + c0 + 16*i);
        #pragma unroll
        for (int i = 0; i < 8; ++i) { ffma2(acc2[0][i], a0, wv[i]); ffma2(acc2[1][i], a1, wv[i]); }
    }
    #pragma unroll
    for (int j = 0; j < 2; ++j) {
        float* op = outp + (size_t)(base + p0 + j) * 128;
        #pragma unroll
        for (int i = 0; i < 8; ++i) {
            float2 v = make_float2(fmaxf(lo2(acc2[j][i]), 0.f), fmaxf(hi2(acc2[j][i]), 0.f));
            *reinterpret_cast<float2*>(op + c0 + 16*i) = v;
        }
    }
}

// ---------------- launch ----------------
extern "C" void kernel_launch(void* const* d_in, const int* in_sizes, int n_in,
                              void* d_out, int out_size)
{
    (void)in_sizes; (void)n_in; (void)out_size;
    const float* x   = (const float*)d_in[0];
    const float* lw1 = (const float*)d_in[1];
    const float* lb1 = (const float*)d_in[2];
    const float* lw2 = (const float*)d_in[3];
    const float* lb2 = (const float*)d_in[4];
    const float* lw3 = (const float*)d_in[5];
    const float* lb3 = (const float*)d_in[6];
    const float* cw1 = (const float*)d_in[7];
    const float* cb1 = (const float*)d_in[8];
    const float* cw2 = (const float*)d_in[9];
    const float* cb2 = (const float*)d_in[10];
    const float* tw1 = (const float*)d_in[11];
    const float* tb1 = (const float*)d_in[12];
    const float* tw2 = (const float*)d_in[13];
    const float* tb2 = (const float*)d_in[14];
    float* out = (float*)d_out;

    const int smB = B_SMEM_FLOATS * 4;
    const int smC = (66*128 + 128 + 16384 + 128 + 64*67 + 64*130) * 4;
    const int smT = (64*128 + 128 + 16384 + 128 + 64*65 + 64*130) * 4;
    cudaFuncSetAttribute(local_mlp_kernel, cudaFuncAttributeMaxDynamicSharedMemorySize, smB);
    cudaFuncSetAttribute(head_kernel<66, 67, true>,  cudaFuncAttributeMaxDynamicSharedMemorySize, smC);
    cudaFuncSetAttribute(head_kernel<64, 65, false>, cudaFuncAttributeMaxDynamicSharedMemorySize, smT);

    knn_geom_kernel<<<dim3(NN/128, 8), 128>>>(x, out);
    local_mlp_kernel<<<NPTS/32, 256, smB>>>(lw1, lb1, lw2, lb2, lw3, lb3);
    head_kernel<66, 67, true ><<<NPTS/64, 256, smC>>>(x, cw1, cb1, cw2, cb2, out);
    head_kernel<64, 65, false><<<NPTS/64, 256, smT>>>(x, tw1, tb1, tw2, tb2, out + OFF_TOPO);
}

// round 9
// speedup vs baseline: 1.0228x; 1.0228x over previous
#include <cuda_runtime.h>
#include <math.h>

#define NN 4096
#define NPTS 32768

typedef unsigned long long ull;

__device__ __forceinline__ ull pack2(float v) {
    ull r; unsigned u = __float_as_uint(v);
    asm("mov.b64 %0,{%1,%1};" : "=l"(r) : "r"(u));
    return r;
}
__device__ __forceinline__ void ffma2(ull &d, ull a, ull b) {
    asm("fma.rn.f32x2 %0, %1, %2, %0;" : "+l"(d) : "l"(a), "l"(b));
}
__device__ __forceinline__ float lo2(ull v) { return __uint_as_float((unsigned)v); }
__device__ __forceinline__ float hi2(ull v) { return __uint_as_float((unsigned)(v >> 32)); }

// scratch (static __device__, no allocation)
__device__ float g_lcc[NPTS * 10];   // (pt, k, xy)
__device__ float g_lf [NPTS * 64];   // local_feats

// out layout: [cls 32768*128 | topo 32768*128 | angle 32768 | axes 32768*2]
#define OFF_TOPO 4194304
#define OFF_ANG  8388608
#define OFF_AX   8421376

// ---------------- Kernel A: KNN (reference-bit-exact dist) + slaev2 eigh + lcc ----------------
__global__ __launch_bounds__(128)
void knn_geom_kernel(const float* __restrict__ xg, float* __restrict__ out)
{
    __shared__ float2 sp[NN];
    __shared__ float  ssq[NN];
    const int b = blockIdx.y;
    const float2* xb = reinterpret_cast<const float2*>(xg) + (size_t)b * NN;
    for (int i = threadIdx.x; i < NN; i += 128) {
        float2 v = xb[i];
        sp[i] = v;
        ssq[i] = __fadd_rn(__fmul_rn(v.x, v.x), __fmul_rn(v.y, v.y));
    }
    __syncthreads();

    const int n = blockIdx.x * 128 + threadIdx.x;
    const float qx = sp[n].x, qy = sp[n].y;
    const float sqn = ssq[n];

    float d0 = 3.4e38f, d1 = 3.4e38f, d2 = 3.4e38f, d3 = 3.4e38f, d4 = 3.4e38f;
    int   i0 = 0, i1 = 0, i2 = 0, i3 = 0, i4 = 0;

    #pragma unroll 4
    for (int m = 0; m < NN; ++m) {
        float2 p = sp[m];
        float dot = __fmaf_rn(p.y, qy, __fmul_rn(p.x, qx));
        float dd = __fsub_rn(__fadd_rn(sqn, ssq[m]), __fmul_rn(2.0f, dot));
        if (dd < d4) {                      // strict <: lax.top_k stable tie-break by index
            if (dd < d3) {
                d4 = d3; i4 = i3;
                if (dd < d2) {
                    d3 = d2; i3 = i2;
                    if (dd < d1) {
                        d2 = d1; i2 = i1;
                        if (dd < d0) { d1 = d0; i1 = i0; d0 = dd; i0 = m; }
                        else          { d1 = dd; i1 = m; }
                    } else { d2 = dd; i2 = m; }
                } else { d3 = dd; i3 = m; }
            } else { d4 = dd; i4 = m; }
        }
    }

    int nb[5] = {i0, i1, i2, i3, i4};
    float rx[5], ry[5];
    #pragma unroll
    for (int k = 0; k < 5; ++k) {
        float2 p = sp[nb[k]];
        rx[k] = __fsub_rn(p.x, qx);
        ry[k] = __fsub_rn(p.y, qy);
    }
    float sxs = __fadd_rn(__fadd_rn(__fadd_rn(__fadd_rn(rx[0], rx[1]), rx[2]), rx[3]), rx[4]);
    float sys = __fadd_rn(__fadd_rn(__fadd_rn(__fadd_rn(ry[0], ry[1]), ry[2]), ry[3]), ry[4]);
    float mx = __fdiv_rn(sxs, 5.0f);
    float my = __fdiv_rn(sys, 5.0f);
    float cx[5], cy[5];
    float sxx = 0.f, sxy = 0.f, syy = 0.f;
    #pragma unroll
    for (int k = 0; k < 5; ++k) {
        cx[k] = __fsub_rn(rx[k], mx);
        cy[k] = __fsub_rn(ry[k], my);
        sxx = __fmaf_rn(cx[k], cx[k], sxx);
        sxy = __fmaf_rn(cx[k], cy[k], sxy);
        syy = __fmaf_rn(cy[k], cy[k], syy);
    }
    float a  = __fadd_rn(__fmul_rn(sxx, 0.25f), 1e-6f);
    float bv = __fmul_rn(sxy, 0.25f);
    float c  = __fadd_rn(__fmul_rn(syy, 0.25f), 1e-6f);

    // ---- LAPACK slaev2 (a,c > 0 => sm > 0 => sgn1 = +1) ----
    float smv = a + c, df = a - c;
    float adf = fabsf(df);
    float tb  = bv + bv;
    float ab  = fabsf(tb);
    float rt;
    if (adf > ab)      { float t = ab / adf; rt = adf * sqrtf(1.f + t*t); }
    else if (adf < ab) { float t = adf / ab; rt = ab * sqrtf(1.f + t*t); }
    else               { rt = ab * 1.4142135623730951f; }
    float rt1 = 0.5f * (smv + rt);
    float acmx, acmn;
    if (fabsf(a) > fabsf(c)) { acmx = a; acmn = c; } else { acmx = c; acmn = a; }
    float rt2 = (acmx / rt1) * acmn - (bv / rt1) * bv;
    float cs; int sgn2;
    if (df >= 0.f) { cs = df + rt; sgn2 = 1; }
    else           { cs = df - rt; sgn2 = -1; }
    float acs = fabsf(cs), cs1, sn1;
    if (acs > ab)       { float ct = -tb / cs; sn1 = 1.f / sqrtf(1.f + ct*ct); cs1 = ct * sn1; }
    else if (ab == 0.f) { cs1 = 1.f; sn1 = 0.f; }
    else                { float tn = -cs / tb; cs1 = 1.f / sqrtf(1.f + tn*tn); sn1 = tn * cs1; }
    if (sgn2 == 1)      { float t = cs1; cs1 = -sn1; sn1 = t; }

    float e0, e1, v00, v10, v01, v11;
    if (rt2 < rt1) { e0 = rt2; e1 = rt1; v00 = -sn1; v10 = cs1; v01 = cs1;  v11 = sn1; }
    else           { e0 = rt1; e1 = rt2; v00 = cs1;  v10 = sn1; v01 = -sn1; v11 = cs1; }

    const int pt = b * NN + n;
    out[OFF_ANG + pt] = atan2f(v11, v01);
    float sL = sqrtf(fmaxf(e1, 1e-6f));
    float sS = sqrtf(fmaxf(e0, 1e-6f));
    float den = fmaxf(sL, sS) + 1e-6f;
    out[OFF_AX + pt * 2 + 0] = fmaxf(sL / den, 0.2f);
    out[OFF_AX + pt * 2 + 1] = fmaxf(sS / den, 0.2f);

    float* lp = g_lcc + (size_t)pt * 10;
    #pragma unroll
    for (int k = 0; k < 5; ++k) {
        lp[2*k]   = __fmaf_rn(cy[k], v10, __fmul_rn(cx[k], v00));
        lp[2*k+1] = __fmaf_rn(cy[k], v11, __fmul_rn(cx[k], v01));
    }
}

// ---------------- Kernel B: local MLP 2->64->128->64 + max over K ----------------
// 32 points/CTA (160 rows), 512 threads. Weight loads warp-uniform LDS.128.
// layout offsets (floats): w1s 0(128) b1s 128(64) w2s 192(8192) b2s 8384(128)
//                          w3s 8512(8192) b3s 16704(64) lccs 16768(320)
//                          h1T 17088(64*161) h2s 27392(160*133)
#define B_SMEM_FLOATS (27392 + 160*133)
__global__ __launch_bounds__(512)
void local_mlp_kernel(const float* __restrict__ lw1, const float* __restrict__ lb1,
                      const float* __restrict__ lw2, const float* __restrict__ lb2,
                      const float* __restrict__ lw3, const float* __restrict__ lb3)
{
    extern __shared__ float smf[];
    float* w1s  = smf;
    float* b1s  = smf + 128;
    float* w2s  = smf + 192;
    float* b2s  = smf + 8384;
    float* w3s  = smf + 8512;
    float* b3s  = smf + 16704;
    float* lccs = smf + 16768;
    float* h1T  = smf + 17088;   // [64][161]  k-major
    float* h2s  = smf + 27392;   // [160][133]

    const int tid  = threadIdx.x;
    const int base = blockIdx.x * 32;

    for (int i = tid; i < 128;  i += 512) { w1s[i] = lw1[i]; b2s[i] = lb2[i]; }
    for (int i = tid; i < 64;   i += 512) { b1s[i] = lb1[i]; b3s[i] = lb3[i]; }
    for (int i = tid; i < 8192; i += 512) { w2s[i] = lw2[i]; w3s[i] = lw3[i]; }
    if (tid < 320) lccs[tid] = g_lcc[(size_t)base * 10 + tid];
    __syncthreads();

    // stage 1: h1 (160x64) -> h1T[c*161 + r]
    for (int idx = tid; idx < 160 * 64; idx += 512) {
        int r = idx >> 6, c = idx & 63;
        float v = fmaf(lccs[2*r], w1s[c], fmaf(lccs[2*r+1], w1s[64 + c], b1s[c]));
        h1T[c * 161 + r] = fmaxf(v, 0.f);
    }
    __syncthreads();

    const int rg = tid & 31;       // row group (= point), 5 rows
    const int cg = tid >> 5;       // 0..15
    const int r0 = rg * 5;

    // stage 2: h2 (160x128), thread tile 5 rows x 8 cols, weights warp-uniform
    {
        const int c0 = cg * 8;
        ull acc[5][4];
        ulonglong2 bp0 = *reinterpret_cast<const ulonglong2*>(b2s + c0);
        ulonglong2 bp1 = *reinterpret_cast<const ulonglong2*>(b2s + c0 + 4);
        #pragma unroll
        for (int j = 0; j < 5; ++j) {
            acc[j][0] = bp0.x; acc[j][1] = bp0.y; acc[j][2] = bp1.x; acc[j][3] = bp1.y;
        }
        for (int k = 0; k < 64; ++k) {
            ull av[5];
            #pragma unroll
            for (int j = 0; j < 5; ++j) av[j] = pack2(h1T[k * 161 + r0 + j]);
            ulonglong2 w0 = *reinterpret_cast<const ulonglong2*>(w2s + k*128 + c0);
            ulonglong2 w1 = *reinterpret_cast<const ulonglong2*>(w2s + k*128 + c0 + 4);
            #pragma unroll
            for (int j = 0; j < 5; ++j) {
                ffma2(acc[j][0], av[j], w0.x);
                ffma2(acc[j][1], av[j], w0.y);
                ffma2(acc[j][2], av[j], w1.x);
                ffma2(acc[j][3], av[j], w1.y);
            }
        }
        #pragma unroll
        for (int j = 0; j < 5; ++j) {
            float* hp = h2s + (r0 + j) * 133 + c0;
            #pragma unroll
            for (int i = 0; i < 4; ++i) {
                hp[2*i]   = fmaxf(lo2(acc[j][i]), 0.f);
                hp[2*i+1] = fmaxf(hi2(acc[j][i]), 0.f);
            }
        }
    }
    __syncthreads();

    // stage 3: h3 (160x64), tile 5 rows x 4 cols, fused relu+max over the 5 neighbors
    {
        const int c0 = cg * 4;
        ull acc3[5][2];
        ulonglong2 bp = *reinterpret_cast<const ulonglong2*>(b3s + c0);
        #pragma unroll
        for (int j = 0; j < 5; ++j) { acc3[j][0] = bp.x; acc3[j][1] = bp.y; }
        for (int k = 0; k < 128; ++k) {
            ull av[5];
            #pragma unroll
            for (int j = 0; j < 5; ++j) av[j] = pack2(h2s[(r0 + j) * 133 + k]);
            ulonglong2 w = *reinterpret_cast<const ulonglong2*>(w3s + k*64 + c0);
            #pragma unroll
            for (int j = 0; j < 5; ++j) {
                ffma2(acc3[j][0], av[j], w.x);
                ffma2(acc3[j][1], av[j], w.y);
            }
        }
        float4 o;
        float m0 = 0.f, m1 = 0.f, m2 = 0.f, m3 = 0.f;   // relu floor
        #pragma unroll
        for (int j = 0; j < 5; ++j) {
            m0 = fmaxf(m0, lo2(acc3[j][0]));
            m1 = fmaxf(m1, hi2(acc3[j][0]));
            m2 = fmaxf(m2, lo2(acc3[j][1]));
            m3 = fmaxf(m3, hi2(acc3[j][1]));
        }
        o.x = m0; o.y = m1; o.z = m2; o.w = m3;
        *reinterpret_cast<float4*>(g_lf + (size_t)(base + rg) * 64 + c0) = o;
    }
}

// ---------------- Kernel C: BOTH heads, 64 points/CTA, 512 threads ----------------
// blockIdx.y: 0 = cls (indim 66, concat x), 1 = topo (indim 64)
// layout (floats): w1s 0(8448) b1s 8448(128) w2s 8576(16384) b2s 24960(128)
//                  ins 25088(64*67) hs 29376(64*131)
#define H_SMEM_FLOATS (29376 + 64*131)
__global__ __launch_bounds__(512)
void head2_kernel(const float* __restrict__ xg,
                  const float* __restrict__ cw1, const float* __restrict__ cb1,
                  const float* __restrict__ cw2, const float* __restrict__ cb2,
                  const float* __restrict__ tw1, const float* __restrict__ tb1,
                  const float* __restrict__ tw2, const float* __restrict__ tb2,
                  float* __restrict__ outg)
{
    extern __shared__ float smf[];
    float* w1s = smf;
    float* b1s = smf + 8448;
    float* w2s = smf + 8576;
    float* b2s = smf + 24960;
    float* ins = smf + 25088;   // [64][67]
    float* hs  = smf + 29376;   // [64][131]

    const int head = blockIdx.y;
    const float* w1 = head ? tw1 : cw1;
    const float* b1 = head ? tb1 : cb1;
    const float* w2 = head ? tw2 : cw2;
    const float* b2 = head ? tb2 : cb2;
    const int indim = head ? 64 : 66;
    const int xoff  = head ? 0 : 2;
    float* outp = outg + (head ? OFF_TOPO : 0);

    const int tid  = threadIdx.x;
    const int base = blockIdx.x * 64;

    for (int i = tid; i < indim * 128; i += 512) w1s[i] = w1[i];
    for (int i = tid; i < 16384;       i += 512) w2s[i] = w2[i];
    if (tid < 128) { b1s[tid] = b1[tid]; b2s[tid] = b2[tid]; }
    for (int idx = tid; idx < 64 * 64; idx += 512) {
        int p = idx >> 6, c = idx & 63;
        ins[p * 67 + xoff + c] = g_lf[(size_t)(base + p) * 64 + c];
    }
    if (!head && tid < 128) {
        int p = tid >> 1, c = tid & 1;
        ins[p * 67 + c] = xg[(size_t)(base + p) * 2 + c];
    }
    __syncthreads();

    const int p  = tid & 63;
    const int c0 = (tid >> 6) * 16;   // warp-uniform column base

    // stage 1: 64 x 128, tile 1 row x 16 cols
    {
        ull acc[8];
        ulonglong2 bq0 = *reinterpret_cast<const ulonglong2*>(b1s + c0);
        ulonglong2 bq1 = *reinterpret_cast<const ulonglong2*>(b1s + c0 + 4);
        ulonglong2 bq2 = *reinterpret_cast<const ulonglong2*>(b1s + c0 + 8);
        ulonglong2 bq3 = *reinterpret_cast<const ulonglong2*>(b1s + c0 + 12);
        acc[0]=bq0.x; acc[1]=bq0.y; acc[2]=bq1.x; acc[3]=bq1.y;
        acc[4]=bq2.x; acc[5]=bq2.y; acc[6]=bq3.x; acc[7]=bq3.y;
        for (int k = 0; k < indim; ++k) {
            ull a = pack2(ins[p * 67 + k]);
            const float* wr = w1s + k * 128 + c0;
            ulonglong2 w0 = *reinterpret_cast<const ulonglong2*>(wr);
            ulonglong2 w1q = *reinterpret_cast<const ulonglong2*>(wr + 4);
            ulonglong2 w2q = *reinterpret_cast<const ulonglong2*>(wr + 8);
            ulonglong2 w3q = *reinterpret_cast<const ulonglong2*>(wr + 12);
            ffma2(acc[0], a, w0.x); ffma2(acc[1], a, w0.y);
            ffma2(acc[2], a, w1q.x); ffma2(acc[3], a, w1q.y);
            ffma2(acc[4], a, w2q.x); ffma2(acc[5], a, w2q.y);
            ffma2(acc[6], a, w3q.x); ffma2(acc[7], a, w3q.y);
        }
        float* hp = hs + p * 131 + c0;
        #pragma unroll
        for (int i = 0; i < 8; ++i) {
            hp[2*i]   = fmaxf(lo2(acc[i]), 0.f);
            hp[2*i+1] = fmaxf(hi2(acc[i]), 0.f);
        }
    }
    __syncthreads();

    // stage 2: 64 x 128
    {
        ull acc[8];
        ulonglong2 bq0 = *reinterpret_cast<const ulonglong2*>(b2s + c0);
        ulonglong2 bq1 = *reinterpret_cast<const ulonglong2*>(b2s + c0 + 4);
        ulonglong2 bq2 = *reinterpret_cast<const ulonglong2*>(b2s + c0 + 8);
        ulonglong2 bq3 = *reinterpret_cast<const ulonglong2*>(b2s + c0 + 12);
        acc[0]=bq0.x; acc[1]=bq0.y; acc[2]=bq1.x; acc[3]=bq1.y;
        acc[4]=bq2.x; acc[5]=bq2.y; acc[6]=bq3.x; acc[7]=bq3.y;
        #pragma unroll 4
        for (int k = 0; k < 128; ++k) {
            ull a = pack2(hs[p * 131 + k]);
            const float* wr = w2s + k * 128 + c0;
            ulonglong2 w0 = *reinterpret_cast<const ulonglong2*>(wr);
            ulonglong2 w1q = *reinterpret_cast<const ulonglong2*>(wr + 4);
            ulonglong2 w2q = *reinterpret_cast<const ulonglong2*>(wr + 8);
            ulonglong2 w3q = *reinterpret_cast<const ulonglong2*>(wr + 12);
            ffma2(acc[0], a, w0.x); ffma2(acc[1], a, w0.y);
            ffma2(acc[2], a, w1q.x); ffma2(acc[3], a, w1q.y);
            ffma2(acc[4], a, w2q.x); ffma2(acc[5], a, w2q.y);
            ffma2(acc[6], a, w3q.x); ffma2(acc[7], a, w3q.y);
        }
        float* op = outp + (size_t)(base + p) * 128 + c0;
        #pragma unroll
        for (int i = 0; i < 8; ++i) {
            float2 v = make_float2(fmaxf(lo2(acc[i]), 0.f), fmaxf(hi2(acc[i]), 0.f));
            *reinterpret_cast<float2*>(op + 2*i) = v;
        }
    }
}

// ---------------- launch ----------------
extern "C" void kernel_launch(void* const* d_in, const int* in_sizes, int n_in,
                              void* d_out, int out_size)
{
    (void)in_sizes; (void)n_in; (void)out_size;
    const float* x   = (const float*)d_in[0];
    const float* lw1 = (const float*)d_in[1];
    const float* lb1 = (const float*)d_in[2];
    const float* lw2 = (const float*)d_in[3];
    const float* lb2 = (const float*)d_in[4];
    const float* lw3 = (const float*)d_in[5];
    const float* lb3 = (const float*)d_in[6];
    const float* cw1 = (const float*)d_in[7];
    const float* cb1 = (const float*)d_in[8];
    const float* cw2 = (const float*)d_in[9];
    const float* cb2 = (const float*)d_in[10];
    const float* tw1 = (const float*)d_in[11];
    const float* tb1 = (const float*)d_in[12];
    const float* tw2 = (const float*)d_in[13];
    const float* tb2 = (const float*)d_in[14];
    float* out = (float*)d_out;

    const int smB = B_SMEM_FLOATS * 4;
    const int smH = H_SMEM_FLOATS * 4;
    cudaFuncSetAttribute(local_mlp_kernel, cudaFuncAttributeMaxDynamicSharedMemorySize, smB);
    cudaFuncSetAttribute(head2_kernel,     cudaFuncAttributeMaxDynamicSharedMemorySize, smH);

    knn_geom_kernel<<<dim3(NN/128, 8), 128>>>(x, out);
    local_mlp_kernel<<<NPTS/32, 512, smB>>>(lw1, lb1, lw2, lb2, lw3, lb3);
    head2_kernel<<<dim3(NPTS/64, 2), 512, smH>>>(x, cw1, cb1, cw2, cb2,
                                                 tw1, tb1, tw2, tb2, out);
}

// round 10
// speedup vs baseline: 1.8602x; 1.8188x over previous
#include <cuda_runtime.h>
#include <math.h>

#define NN 4096
#define NPTS 32768
#define SLICES 4
#define SLICE_N 1024

typedef unsigned long long ull;

__device__ __forceinline__ ull pack2(float v) {
    ull r; unsigned u = __float_as_uint(v);
    asm("mov.b64 %0,{%1,%1};" : "=l"(r) : "r"(u));
    return r;
}
__device__ __forceinline__ ull pack2f(float lo, float hi) {
    ull r;
    asm("mov.b64 %0,{%1,%2};" : "=l"(r) : "r"(__float_as_uint(lo)), "r"(__float_as_uint(hi)));
    return r;
}
__device__ __forceinline__ void ffma2(ull &d, ull a, ull b) {
    asm("fma.rn.f32x2 %0, %1, %2, %0;" : "+l"(d) : "l"(a), "l"(b));
}
__device__ __forceinline__ ull mul2(ull a, ull b) {
    ull r; asm("mul.rn.f32x2 %0, %1, %2;" : "=l"(r) : "l"(a), "l"(b)); return r;
}
__device__ __forceinline__ ull add2(ull a, ull b) {
    ull r; asm("add.rn.f32x2 %0, %1, %2;" : "=l"(r) : "l"(a), "l"(b)); return r;
}
__device__ __forceinline__ ull fma2v(ull a, ull b, ull c) {
    ull r; asm("fma.rn.f32x2 %0, %1, %2, %3;" : "=l"(r) : "l"(a), "l"(b), "l"(c)); return r;
}
__device__ __forceinline__ float lo2(ull v) { return __uint_as_float((unsigned)v); }
__device__ __forceinline__ float hi2(ull v) { return __uint_as_float((unsigned)(v >> 32)); }

// scratch (static __device__, no allocation)
__device__ float g_lcc[NPTS * 10];        // (pt, k, xy)
__device__ float g_lf [NPTS * 64];        // local_feats
__device__ float g_pd [NPTS * 20];        // partial top-5 dists, 4 slices
__device__ int   g_pi [NPTS * 20];        // partial top-5 indices

// out layout: [cls 32768*128 | topo 32768*128 | angle 32768 | axes 32768*2]
#define OFF_TOPO 4194304
#define OFF_ANG  8388608
#define OFF_AX   8421376

// insert (dd, mi) into sorted-ascending register top-5 with strict < (stable by index)
#define INS5(dd, mi)                                                        \
    if (dd < d4) {                                                          \
        if (dd < d3) {                                                      \
            d4 = d3; i4 = i3;                                               \
            if (dd < d2) {                                                  \
                d3 = d2; i3 = i2;                                           \
                if (dd < d1) {                                              \
                    d2 = d1; i2 = i1;                                       \
                    if (dd < d0) { d1 = d0; i1 = i0; d0 = dd; i0 = mi; }    \
                    else          { d1 = dd; i1 = mi; }                     \
                } else { d2 = dd; i2 = mi; }                                \
            } else { d3 = dd; i3 = mi; }                                    \
        } else { d4 = dd; i4 = mi; }                                        \
    }

// ---------------- Kernel A1: partial KNN over one candidate slice (packed f32x2) ----------------
__global__ __launch_bounds__(128)
void knn_part_kernel(const float* __restrict__ xg)
{
    __shared__ ull sx[SLICE_N / 2];   // packed x pairs
    __shared__ ull sy[SLICE_N / 2];   // packed y pairs
    __shared__ ull sq[SLICE_N / 2];   // packed sq pairs

    const int b  = blockIdx.z;
    const int s  = blockIdx.y;
    const int m0 = s * SLICE_N;
    const float2* xb = reinterpret_cast<const float2*>(xg) + (size_t)b * NN;

    for (int i = threadIdx.x; i < SLICE_N / 2; i += 128) {
        float2 p0 = xb[m0 + 2*i];
        float2 p1 = xb[m0 + 2*i + 1];
        sx[i] = pack2f(p0.x, p1.x);
        sy[i] = pack2f(p0.y, p1.y);
        // sq = rn(x*x) + rn(y*y)  (jnp.sum(x*x,-1), no fma)
        float q0 = __fadd_rn(__fmul_rn(p0.x, p0.x), __fmul_rn(p0.y, p0.y));
        float q1 = __fadd_rn(__fmul_rn(p1.x, p1.x), __fmul_rn(p1.y, p1.y));
        sq[i] = pack2f(q0, q1);
    }
    __syncthreads();

    const int n = blockIdx.x * 128 + threadIdx.x;
    float2 qv = xb[n];
    const float sqn = __fadd_rn(__fmul_rn(qv.x, qv.x), __fmul_rn(qv.y, qv.y));
    const ull QX = pack2(qv.x), QY = pack2(qv.y), SQN = pack2(sqn), NEG2 = pack2(-2.0f);

    float d0 = 3.4e38f, d1 = 3.4e38f, d2 = 3.4e38f, d3 = 3.4e38f, d4 = 3.4e38f;
    int   i0 = 0, i1 = 0, i2 = 0, i3 = 0, i4 = 0;

    #pragma unroll 4
    for (int j = 0; j < SLICE_N / 2; ++j) {
        ull X = sx[j], Y = sy[j], S = sq[j];
        // dot = fma(y, qy, rn(x*qx))  (Eigen k=2 fold), dd = rn(sum - 2*dot)
        ull dot = fma2v(Y, QY, mul2(X, QX));
        ull sum = add2(SQN, S);
        ull ddp = fma2v(dot, NEG2, sum);   // exact: 2*dot has no rounding
        float ddlo = lo2(ddp), ddhi = hi2(ddp);
        int mi = m0 + 2*j;
        INS5(ddlo, mi);
        INS5(ddhi, mi + 1);
    }

    float* pd = g_pd + ((size_t)(b * NN + n)) * 20 + s * 5;
    int*   pi = g_pi + ((size_t)(b * NN + n)) * 20 + s * 5;
    pd[0] = d0; pd[1] = d1; pd[2] = d2; pd[3] = d3; pd[4] = d4;
    pi[0] = i0; pi[1] = i1; pi[2] = i2; pi[3] = i3; pi[4] = i4;
}

// ---------------- Kernel A2: merge partials + slaev2 eigh + lcc ----------------
__global__ __launch_bounds__(128)
void knn_merge_geom_kernel(const float* __restrict__ xg, float* __restrict__ out)
{
    const int pt = blockIdx.x * 128 + threadIdx.x;
    const int b  = pt >> 12;
    const int n  = pt & (NN - 1);
    const float2* xb = reinterpret_cast<const float2*>(xg) + (size_t)b * NN;

    float pd[20]; int pi[20];
    {
        const float* gp = g_pd + (size_t)pt * 20;
        const int*   gi = g_pi + (size_t)pt * 20;
        #pragma unroll
        for (int j = 0; j < 20; ++j) { pd[j] = gp[j]; pi[j] = gi[j]; }
    }

    // exact global top-5 by (d, idx) lexicographic (== lax.top_k stable order)
    int nb[5];
    unsigned used = 0;
    #pragma unroll
    for (int k = 0; k < 5; ++k) {
        float best = 3.5e38f; int bidx = 0x7fffffff; int bj = 0;
        #pragma unroll
        for (int j = 0; j < 20; ++j) {
            bool freej = !((used >> j) & 1u);
            float dj = pd[j]; int ij = pi[j];
            if (freej && (dj < best || (dj == best && ij < bidx))) {
                best = dj; bidx = ij; bj = j;
            }
        }
        used |= 1u << bj;
        nb[k] = bidx;
    }

    const float qx = xb[n].x, qy = xb[n].y;
    float rx[5], ry[5];
    #pragma unroll
    for (int k = 0; k < 5; ++k) {
        float2 p = xb[nb[k]];
        rx[k] = __fsub_rn(p.x, qx);
        ry[k] = __fsub_rn(p.y, qy);
    }
    float sxs = __fadd_rn(__fadd_rn(__fadd_rn(__fadd_rn(rx[0], rx[1]), rx[2]), rx[3]), rx[4]);
    float sys = __fadd_rn(__fadd_rn(__fadd_rn(__fadd_rn(ry[0], ry[1]), ry[2]), ry[3]), ry[4]);
    float mx = __fdiv_rn(sxs, 5.0f);
    float my = __fdiv_rn(sys, 5.0f);
    float cx[5], cy[5];
    float sxx = 0.f, sxy = 0.f, syy = 0.f;
    #pragma unroll
    for (int k = 0; k < 5; ++k) {
        cx[k] = __fsub_rn(rx[k], mx);
        cy[k] = __fsub_rn(ry[k], my);
        sxx = __fmaf_rn(cx[k], cx[k], sxx);
        sxy = __fmaf_rn(cx[k], cy[k], sxy);
        syy = __fmaf_rn(cy[k], cy[k], syy);
    }
    float a  = __fadd_rn(__fmul_rn(sxx, 0.25f), 1e-6f);
    float bv = __fmul_rn(sxy, 0.25f);
    float c  = __fadd_rn(__fmul_rn(syy, 0.25f), 1e-6f);

    // ---- LAPACK slaev2 (a,c > 0 => sm > 0 => sgn1 = +1) ----
    float smv = a + c, df = a - c;
    float adf = fabsf(df);
    float tb  = bv + bv;
    float ab  = fabsf(tb);
    float rt;
    if (adf > ab)      { float t = ab / adf; rt = adf * sqrtf(1.f + t*t); }
    else if (adf < ab) { float t = adf / ab; rt = ab * sqrtf(1.f + t*t); }
    else               { rt = ab * 1.4142135623730951f; }
    float rt1 = 0.5f * (smv + rt);
    float acmx, acmn;
    if (fabsf(a) > fabsf(c)) { acmx = a; acmn = c; } else { acmx = c; acmn = a; }
    float rt2 = (acmx / rt1) * acmn - (bv / rt1) * bv;
    float cs; int sgn2;
    if (df >= 0.f) { cs = df + rt; sgn2 = 1; }
    else           { cs = df - rt; sgn2 = -1; }
    float acs = fabsf(cs), cs1, sn1;
    if (acs > ab)       { float ct = -tb / cs; sn1 = 1.f / sqrtf(1.f + ct*ct); cs1 = ct * sn1; }
    else if (ab == 0.f) { cs1 = 1.f; sn1 = 0.f; }
    else                { float tn = -cs / tb; cs1 = 1.f / sqrtf(1.f + tn*tn); sn1 = tn * cs1; }
    if (sgn2 == 1)      { float t = cs1; cs1 = -sn1; sn1 = t; }

    float e0, e1, v00, v10, v01, v11;
    if (rt2 < rt1) { e0 = rt2; e1 = rt1; v00 = -sn1; v10 = cs1; v01 = cs1;  v11 = sn1; }
    else           { e0 = rt1; e1 = rt2; v00 = cs1;  v10 = sn1; v01 = -sn1; v11 = cs1; }

    out[OFF_ANG + pt] = atan2f(v11, v01);
    float sL = sqrtf(fmaxf(e1, 1e-6f));
    float sS = sqrtf(fmaxf(e0, 1e-6f));
    float den = fmaxf(sL, sS) + 1e-6f;
    out[OFF_AX + pt * 2 + 0] = fmaxf(sL / den, 0.2f);
    out[OFF_AX + pt * 2 + 1] = fmaxf(sS / den, 0.2f);

    float* lp = g_lcc + (size_t)pt * 10;
    #pragma unroll
    for (int k = 0; k < 5; ++k) {
        lp[2*k]   = __fmaf_rn(cy[k], v10, __fmul_rn(cx[k], v00));
        lp[2*k+1] = __fmaf_rn(cy[k], v11, __fmul_rn(cx[k], v01));
    }
}

// ---------------- Kernel B: local MLP 2->64->128->64 + max over K ----------------
// 32 points/CTA (160 rows), 512 threads. Weight loads warp-uniform LDS.128.
#define B_SMEM_FLOATS (27392 + 160*133)
__global__ __launch_bounds__(512)
void local_mlp_kernel(const float* __restrict__ lw1, const float* __restrict__ lb1,
                      const float* __restrict__ lw2, const float* __restrict__ lb2,
                      const float* __restrict__ lw3, const float* __restrict__ lb3)
{
    extern __shared__ float smf[];
    float* w1s  = smf;
    float* b1s  = smf + 128;
    float* w2s  = smf + 192;
    float* b2s  = smf + 8384;
    float* w3s  = smf + 8512;
    float* b3s  = smf + 16704;
    float* lccs = smf + 16768;
    float* h1T  = smf + 17088;   // [64][161]  k-major
    float* h2s  = smf + 27392;   // [160][133]

    const int tid  = threadIdx.x;
    const int base = blockIdx.x * 32;

    for (int i = tid; i < 128;  i += 512) { w1s[i] = lw1[i]; b2s[i] = lb2[i]; }
    for (int i = tid; i < 64;   i += 512) { b1s[i] = lb1[i]; b3s[i] = lb3[i]; }
    for (int i = tid; i < 8192; i += 512) { w2s[i] = lw2[i]; w3s[i] = lw3[i]; }
    if (tid < 320) lccs[tid] = g_lcc[(size_t)base * 10 + tid];
    __syncthreads();

    // stage 1: h1 (160x64) -> h1T[c*161 + r]
    for (int idx = tid; idx < 160 * 64; idx += 512) {
        int r = idx >> 6, c = idx & 63;
        float v = fmaf(lccs[2*r], w1s[c], fmaf(lccs[2*r+1], w1s[64 + c], b1s[c]));
        h1T[c * 161 + r] = fmaxf(v, 0.f);
    }
    __syncthreads();

    const int rg = tid & 31;       // point
    const int cg = tid >> 5;       // 0..15
    const int r0 = rg * 5;

    // stage 2: h2 (160x128), tile 5 rows x 8 cols, weights warp-uniform
    {
        const int c0 = cg * 8;
        ull acc[5][4];
        ulonglong2 bp0 = *reinterpret_cast<const ulonglong2*>(b2s + c0);
        ulonglong2 bp1 = *reinterpret_cast<const ulonglong2*>(b2s + c0 + 4);
        #pragma unroll
        for (int j = 0; j < 5; ++j) {
            acc[j][0] = bp0.x; acc[j][1] = bp0.y; acc[j][2] = bp1.x; acc[j][3] = bp1.y;
        }
        for (int k = 0; k < 64; ++k) {
            ull av[5];
            #pragma unroll
            for (int j = 0; j < 5; ++j) av[j] = pack2(h1T[k * 161 + r0 + j]);
            ulonglong2 w0 = *reinterpret_cast<const ulonglong2*>(w2s + k*128 + c0);
            ulonglong2 w1 = *reinterpret_cast<const ulonglong2*>(w2s + k*128 + c0 + 4);
            #pragma unroll
            for (int j = 0; j < 5; ++j) {
                ffma2(acc[j][0], av[j], w0.x);
                ffma2(acc[j][1], av[j], w0.y);
                ffma2(acc[j][2], av[j], w1.x);
                ffma2(acc[j][3], av[j], w1.y);
            }
        }
        #pragma unroll
        for (int j = 0; j < 5; ++j) {
            float* hp = h2s + (r0 + j) * 133 + c0;
            #pragma unroll
            for (int i = 0; i < 4; ++i) {
                hp[2*i]   = fmaxf(lo2(acc[j][i]), 0.f);
                hp[2*i+1] = fmaxf(hi2(acc[j][i]), 0.f);
            }
        }
    }
    __syncthreads();

    // stage 3: h3 (160x64), tile 5 rows x 4 cols, fused relu+max over 5 neighbors
    {
        const int c0 = cg * 4;
        ull acc3[5][2];
        ulonglong2 bp = *reinterpret_cast<const ulonglong2*>(b3s + c0);
        #pragma unroll
        for (int j = 0; j < 5; ++j) { acc3[j][0] = bp.x; acc3[j][1] = bp.y; }
        for (int k = 0; k < 128; ++k) {
            ull av[5];
            #pragma unroll
            for (int j = 0; j < 5; ++j) av[j] = pack2(h2s[(r0 + j) * 133 + k]);
            ulonglong2 w = *reinterpret_cast<const ulonglong2*>(w3s + k*64 + c0);
            #pragma unroll
            for (int j = 0; j < 5; ++j) {
                ffma2(acc3[j][0], av[j], w.x);
                ffma2(acc3[j][1], av[j], w.y);
            }
        }
        float4 o;
        float m0 = 0.f, m1 = 0.f, m2 = 0.f, m3 = 0.f;   // relu floor
        #pragma unroll
        for (int j = 0; j < 5; ++j) {
            m0 = fmaxf(m0, lo2(acc3[j][0]));
            m1 = fmaxf(m1, hi2(acc3[j][0]));
            m2 = fmaxf(m2, lo2(acc3[j][1]));
            m3 = fmaxf(m3, hi2(acc3[j][1]));
        }
        o.x = m0; o.y = m1; o.z = m2; o.w = m3;
        *reinterpret_cast<float4*>(g_lf + (size_t)(base + rg) * 64 + c0) = o;
    }
}

// ---------------- Kernel C: BOTH heads, 64 points/CTA, 512 threads ----------------
#define H_SMEM_FLOATS (29376 + 64*131)
__global__ __launch_bounds__(512)
void head2_kernel(const float* __restrict__ xg,
                  const float* __restrict__ cw1, const float* __restrict__ cb1,
                  const float* __restrict__ cw2, const float* __restrict__ cb2,
                  const float* __restrict__ tw1, const float* __restrict__ tb1,
                  const float* __restrict__ tw2, const float* __restrict__ tb2,
                  float* __restrict__ outg)
{
    extern __shared__ float smf[];
    float* w1s = smf;
    float* b1s = smf + 8448;
    float* w2s = smf + 8576;
    float* b2s = smf + 24960;
    float* ins = smf + 25088;   // [64][67]
    float* hs  = smf + 29376;   // [64][131]

    const int head = blockIdx.y;
    const float* w1 = head ? tw1 : cw1;
    const float* b1 = head ? tb1 : cb1;
    const float* w2 = head ? tw2 : cw2;
    const float* b2 = head ? tb2 : cb2;
    const int indim = head ? 64 : 66;
    const int xoff  = head ? 0 : 2;
    float* outp = outg + (head ? OFF_TOPO : 0);

    const int tid  = threadIdx.x;
    const int base = blockIdx.x * 64;

    for (int i = tid; i < indim * 128; i += 512) w1s[i] = w1[i];
    for (int i = tid; i < 16384;       i += 512) w2s[i] = w2[i];
    if (tid < 128) { b1s[tid] = b1[tid]; b2s[tid] = b2[tid]; }
    for (int idx = tid; idx < 64 * 64; idx += 512) {
        int p = idx >> 6, c = idx & 63;
        ins[p * 67 + xoff + c] = g_lf[(size_t)(base + p) * 64 + c];
    }
    if (!head && tid < 128) {
        int p = tid >> 1, c = tid & 1;
        ins[p * 67 + c] = xg[(size_t)(base + p) * 2 + c];
    }
    __syncthreads();

    const int p  = tid & 63;
    const int c0 = (tid >> 6) * 16;   // warp-uniform column base

    // stage 1: 64 x 128, tile 1 row x 16 cols
    {
        ull acc[8];
        ulonglong2 bq0 = *reinterpret_cast<const ulonglong2*>(b1s + c0);
        ulonglong2 bq1 = *reinterpret_cast<const ulonglong2*>(b1s + c0 + 4);
        ulonglong2 bq2 = *reinterpret_cast<const ulonglong2*>(b1s + c0 + 8);
        ulonglong2 bq3 = *reinterpret_cast<const ulonglong2*>(b1s + c0 + 12);
        acc[0]=bq0.x; acc[1]=bq0.y; acc[2]=bq1.x; acc[3]=bq1.y;
        acc[4]=bq2.x; acc[5]=bq2.y; acc[6]=bq3.x; acc[7]=bq3.y;
        for (int k = 0; k < indim; ++k) {
            ull a = pack2(ins[p * 67 + k]);
            const float* wr = w1s + k * 128 + c0;
            ulonglong2 w0 = *reinterpret_cast<const ulonglong2*>(wr);
            ulonglong2 w1q = *reinterpret_cast<const ulonglong2*>(wr + 4);
            ulonglong2 w2q = *reinterpret_cast<const ulonglong2*>(wr + 8);
            ulonglong2 w3q = *reinterpret_cast<const ulonglong2*>(wr + 12);
            ffma2(acc[0], a, w0.x); ffma2(acc[1], a, w0.y);
            ffma2(acc[2], a, w1q.x); ffma2(acc[3], a, w1q.y);
            ffma2(acc[4], a, w2q.x); ffma2(acc[5], a, w2q.y);
            ffma2(acc[6], a, w3q.x); ffma2(acc[7], a, w3q.y);
        }
        float* hp = hs + p * 131 + c0;
        #pragma unroll
        for (int i = 0; i < 8; ++i) {
            hp[2*i]   = fmaxf(lo2(acc[i]), 0.f);
            hp[2*i+1] = fmaxf(hi2(acc[i]), 0.f);
        }
    }
    __syncthreads();

    // stage 2: 64 x 128
    {
        ull acc[8];
        ulonglong2 bq0 = *reinterpret_cast<const ulonglong2*>(b2s + c0);
        ulonglong2 bq1 = *reinterpret_cast<const ulonglong2*>(b2s + c0 + 4);
        ulonglong2 bq2 = *reinterpret_cast<const ulonglong2*>(b2s + c0 + 8);
        ulonglong2 bq3 = *reinterpret_cast<const ulonglong2*>(b2s + c0 + 12);
        acc[0]=bq0.x; acc[1]=bq0.y; acc[2]=bq1.x; acc[3]=bq1.y;
        acc[4]=bq2.x; acc[5]=bq2.y; acc[6]=bq3.x; acc[7]=bq3.y;
        #pragma unroll 4
        for (int k = 0; k < 128; ++k) {
            ull a = pack2(hs[p * 131 + k]);
            const float* wr = w2s + k * 128 + c0;
            ulonglong2 w0 = *reinterpret_cast<const ulonglong2*>(wr);
            ulonglong2 w1q = *reinterpret_cast<const ulonglong2*>(wr + 4);
            ulonglong2 w2q = *reinterpret_cast<const ulonglong2*>(wr + 8);
            ulonglong2 w3q = *reinterpret_cast<const ulonglong2*>(wr + 12);
            ffma2(acc[0], a, w0.x); ffma2(acc[1], a, w0.y);
            ffma2(acc[2], a, w1q.x); ffma2(acc[3], a, w1q.y);
            ffma2(acc[4], a, w2q.x); ffma2(acc[5], a, w2q.y);
            ffma2(acc[6], a, w3q.x); ffma2(acc[7], a, w3q.y);
        }
        float* op = outp + (size_t)(base + p) * 128 + c0;
        #pragma unroll
        for (int i = 0; i < 8; ++i) {
            float2 v = make_float2(fmaxf(lo2(acc[i]), 0.f), fmaxf(hi2(acc[i]), 0.f));
            *reinterpret_cast<float2*>(op + 2*i) = v;
        }
    }
}

// ---------------- launch ----------------
extern "C" void kernel_launch(void* const* d_in, const int* in_sizes, int n_in,
                              void* d_out, int out_size)
{
    (void)in_sizes; (void)n_in; (void)out_size;
    const float* x   = (const float*)d_in[0];
    const float* lw1 = (const float*)d_in[1];
    const float* lb1 = (const float*)d_in[2];
    const float* lw2 = (const float*)d_in[3];
    const float* lb2 = (const float*)d_in[4];
    const float* lw3 = (const float*)d_in[5];
    const float* lb3 = (const float*)d_in[6];
    const float* cw1 = (const float*)d_in[7];
    const float* cb1 = (const float*)d_in[8];
    const float* cw2 = (const float*)d_in[9];
    const float* cb2 = (const float*)d_in[10];
    const float* tw1 = (const float*)d_in[11];
    const float* tb1 = (const float*)d_in[12];
    const float* tw2 = (const float*)d_in[13];
    const float* tb2 = (const float*)d_in[14];
    float* out = (float*)d_out;

    const int smB = B_SMEM_FLOATS * 4;
    const int smH = H_SMEM_FLOATS * 4;
    cudaFuncSetAttribute(local_mlp_kernel, cudaFuncAttributeMaxDynamicSharedMemorySize, smB);
    cudaFuncSetAttribute(head2_kernel,     cudaFuncAttributeMaxDynamicSharedMemorySize, smH);

    knn_part_kernel<<<dim3(NN/128, SLICES, 8), 128>>>(x);
    knn_merge_geom_kernel<<<NPTS/128, 128>>>(x, out);
    local_mlp_kernel<<<NPTS/32, 512, smB>>>(lw1, lb1, lw2, lb2, lw3, lb3);
    head2_kernel<<<dim3(NPTS/64, 2), 512, smH>>>(x, cw1, cb1, cw2, cb2,
                                                 tw1, tb1, tw2, tb2, out);
}

// round 11
// speedup vs baseline: 1.9131x; 1.0284x over previous
#include <cuda_runtime.h>
#include <math.h>

#define NN 4096
#define NPTS 32768
#define SLICES 4
#define SLICE_N 1024

typedef unsigned long long ull;

__device__ __forceinline__ ull pack2(float v) {
    ull r; unsigned u = __float_as_uint(v);
    asm("mov.b64 %0,{%1,%1};" : "=l"(r) : "r"(u));
    return r;
}
__device__ __forceinline__ ull pack2f(float lo, float hi) {
    ull r;
    asm("mov.b64 %0,{%1,%2};" : "=l"(r) : "r"(__float_as_uint(lo)), "r"(__float_as_uint(hi)));
    return r;
}
__device__ __forceinline__ void ffma2(ull &d, ull a, ull b) {
    asm("fma.rn.f32x2 %0, %1, %2, %0;" : "+l"(d) : "l"(a), "l"(b));
}
__device__ __forceinline__ ull mul2(ull a, ull b) {
    ull r; asm("mul.rn.f32x2 %0, %1, %2;" : "=l"(r) : "l"(a), "l"(b)); return r;
}
__device__ __forceinline__ ull add2(ull a, ull b) {
    ull r; asm("add.rn.f32x2 %0, %1, %2;" : "=l"(r) : "l"(a), "l"(b)); return r;
}
__device__ __forceinline__ ull fma2v(ull a, ull b, ull c) {
    ull r; asm("fma.rn.f32x2 %0, %1, %2, %3;" : "=l"(r) : "l"(a), "l"(b), "l"(c)); return r;
}
__device__ __forceinline__ float lo2(ull v) { return __uint_as_float((unsigned)v); }
__device__ __forceinline__ float hi2(ull v) { return __uint_as_float((unsigned)(v >> 32)); }

// scratch (static __device__, no allocation)
__device__ float g_lcc[NPTS * 10];        // (pt, k, xy)
__device__ float g_lf [NPTS * 64];        // local_feats
__device__ float g_pd [NPTS * 20];        // partial top-5 dists, 4 slices
__device__ int   g_pi [NPTS * 20];        // partial top-5 indices

// out layout: [cls 32768*128 | topo 32768*128 | angle 32768 | axes 32768*2]
#define OFF_TOPO 4194304
#define OFF_ANG  8388608
#define OFF_AX   8421376

// insert (dd, mi) into sorted-ascending register top-5 with strict < (stable by index)
#define INS5(dd, mi)                                                        \
    if (dd < d4) {                                                          \
        if (dd < d3) {                                                      \
            d4 = d3; i4 = i3;                                               \
            if (dd < d2) {                                                  \
                d3 = d2; i3 = i2;                                           \
                if (dd < d1) {                                              \
                    d2 = d1; i2 = i1;                                       \
                    if (dd < d0) { d1 = d0; i1 = i0; d0 = dd; i0 = mi; }    \
                    else          { d1 = dd; i1 = mi; }                     \
                } else { d2 = dd; i2 = mi; }                                \
            } else { d3 = dd; i3 = mi; }                                    \
        } else { d4 = dd; i4 = mi; }                                        \
    }

// ---------------- Kernel A1: partial KNN over one candidate slice (packed f32x2) ----------------
__global__ __launch_bounds__(128)
void knn_part_kernel(const float* __restrict__ xg)
{
    __shared__ ull sx[SLICE_N / 2];   // packed x pairs
    __shared__ ull sy[SLICE_N / 2];   // packed y pairs
    __shared__ ull sq[SLICE_N / 2];   // packed sq pairs

    const int b  = blockIdx.z;
    const int s  = blockIdx.y;
    const int m0 = s * SLICE_N;
    const float2* xb = reinterpret_cast<const float2*>(xg) + (size_t)b * NN;

    for (int i = threadIdx.x; i < SLICE_N / 2; i += 128) {
        float2 p0 = xb[m0 + 2*i];
        float2 p1 = xb[m0 + 2*i + 1];
        sx[i] = pack2f(p0.x, p1.x);
        sy[i] = pack2f(p0.y, p1.y);
        // sq = rn(x*x) + rn(y*y)  (jnp.sum(x*x,-1), no fma)
        float q0 = __fadd_rn(__fmul_rn(p0.x, p0.x), __fmul_rn(p0.y, p0.y));
        float q1 = __fadd_rn(__fmul_rn(p1.x, p1.x), __fmul_rn(p1.y, p1.y));
        sq[i] = pack2f(q0, q1);
    }
    __syncthreads();

    const int n = blockIdx.x * 128 + threadIdx.x;
    float2 qv = xb[n];
    const float sqn = __fadd_rn(__fmul_rn(qv.x, qv.x), __fmul_rn(qv.y, qv.y));
    const ull QX = pack2(qv.x), QY = pack2(qv.y), SQN = pack2(sqn), NEG2 = pack2(-2.0f);

    float d0 = 3.4e38f, d1 = 3.4e38f, d2 = 3.4e38f, d3 = 3.4e38f, d4 = 3.4e38f;
    int   i0 = 0, i1 = 0, i2 = 0, i3 = 0, i4 = 0;

    #pragma unroll 4
    for (int j = 0; j < SLICE_N / 2; ++j) {
        ull X = sx[j], Y = sy[j], S = sq[j];
        // dot = fma(y, qy, rn(x*qx))  (Eigen k=2 fold), dd = rn(sum - 2*dot)
        ull dot = fma2v(Y, QY, mul2(X, QX));
        ull sum = add2(SQN, S);
        ull ddp = fma2v(dot, NEG2, sum);   // exact: 2*dot has no rounding
        float ddlo = lo2(ddp), ddhi = hi2(ddp);
        int mi = m0 + 2*j;
        INS5(ddlo, mi);
        INS5(ddhi, mi + 1);
    }

    float* pd = g_pd + ((size_t)(b * NN + n)) * 20 + s * 5;
    int*   pi = g_pi + ((size_t)(b * NN + n)) * 20 + s * 5;
    pd[0] = d0; pd[1] = d1; pd[2] = d2; pd[3] = d3; pd[4] = d4;
    pi[0] = i0; pi[1] = i1; pi[2] = i2; pi[3] = i3; pi[4] = i4;
}

// ---------------- Kernel A2: merge partials + slaev2 eigh + lcc ----------------
__global__ __launch_bounds__(128)
void knn_merge_geom_kernel(const float* __restrict__ xg, float* __restrict__ out)
{
    const int pt = blockIdx.x * 128 + threadIdx.x;
    const int b  = pt >> 12;
    const int n  = pt & (NN - 1);
    const float2* xb = reinterpret_cast<const float2*>(xg) + (size_t)b * NN;

    float pd[20]; int pi[20];
    {
        const float* gp = g_pd + (size_t)pt * 20;
        const int*   gi = g_pi + (size_t)pt * 20;
        #pragma unroll
        for (int j = 0; j < 20; ++j) { pd[j] = gp[j]; pi[j] = gi[j]; }
    }

    // exact global top-5 by (d, idx) lexicographic (== lax.top_k stable order)
    int nb[5];
    unsigned used = 0;
    #pragma unroll
    for (int k = 0; k < 5; ++k) {
        float best = 3.5e38f; int bidx = 0x7fffffff; int bj = 0;
        #pragma unroll
        for (int j = 0; j < 20; ++j) {
            bool freej = !((used >> j) & 1u);
            float dj = pd[j]; int ij = pi[j];
            if (freej && (dj < best || (dj == best && ij < bidx))) {
                best = dj; bidx = ij; bj = j;
            }
        }
        used |= 1u << bj;
        nb[k] = bidx;
    }

    const float qx = xb[n].x, qy = xb[n].y;
    float rx[5], ry[5];
    #pragma unroll
    for (int k = 0; k < 5; ++k) {
        float2 p = xb[nb[k]];
        rx[k] = __fsub_rn(p.x, qx);
        ry[k] = __fsub_rn(p.y, qy);
    }
    float sxs = __fadd_rn(__fadd_rn(__fadd_rn(__fadd_rn(rx[0], rx[1]), rx[2]), rx[3]), rx[4]);
    float sys = __fadd_rn(__fadd_rn(__fadd_rn(__fadd_rn(ry[0], ry[1]), ry[2]), ry[3]), ry[4]);
    float mx = __fdiv_rn(sxs, 5.0f);
    float my = __fdiv_rn(sys, 5.0f);
    float cx[5], cy[5];
    float sxx = 0.f, sxy = 0.f, syy = 0.f;
    #pragma unroll
    for (int k = 0; k < 5; ++k) {
        cx[k] = __fsub_rn(rx[k], mx);
        cy[k] = __fsub_rn(ry[k], my);
        sxx = __fmaf_rn(cx[k], cx[k], sxx);
        sxy = __fmaf_rn(cx[k], cy[k], sxy);
        syy = __fmaf_rn(cy[k], cy[k], syy);
    }
    float a  = __fadd_rn(__fmul_rn(sxx, 0.25f), 1e-6f);
    float bv = __fmul_rn(sxy, 0.25f);
    float c  = __fadd_rn(__fmul_rn(syy, 0.25f), 1e-6f);

    // ---- LAPACK slaev2 (a,c > 0 => sm > 0 => sgn1 = +1) ----
    float smv = a + c, df = a - c;
    float adf = fabsf(df);
    float tb  = bv + bv;
    float ab  = fabsf(tb);
    float rt;
    if (adf > ab)      { float t = ab / adf; rt = adf * sqrtf(1.f + t*t); }
    else if (adf < ab) { float t = adf / ab; rt = ab * sqrtf(1.f + t*t); }
    else               { rt = ab * 1.4142135623730951f; }
    float rt1 = 0.5f * (smv + rt);
    float acmx, acmn;
    if (fabsf(a) > fabsf(c)) { acmx = a; acmn = c; } else { acmx = c; acmn = a; }
    float rt2 = (acmx / rt1) * acmn - (bv / rt1) * bv;
    float cs; int sgn2;
    if (df >= 0.f) { cs = df + rt; sgn2 = 1; }
    else           { cs = df - rt; sgn2 = -1; }
    float acs = fabsf(cs), cs1, sn1;
    if (acs > ab)       { float ct = -tb / cs; sn1 = 1.f / sqrtf(1.f + ct*ct); cs1 = ct * sn1; }
    else if (ab == 0.f) { cs1 = 1.f; sn1 = 0.f; }
    else                { float tn = -cs / tb; cs1 = 1.f / sqrtf(1.f + tn*tn); sn1 = tn * cs1; }
    if (sgn2 == 1)      { float t = cs1; cs1 = -sn1; sn1 = t; }

    float e0, e1, v00, v10, v01, v11;
    if (rt2 < rt1) { e0 = rt2; e1 = rt1; v00 = -sn1; v10 = cs1; v01 = cs1;  v11 = sn1; }
    else           { e0 = rt1; e1 = rt2; v00 = cs1;  v10 = sn1; v01 = -sn1; v11 = cs1; }

    out[OFF_ANG + pt] = atan2f(v11, v01);
    float sL = sqrtf(fmaxf(e1, 1e-6f));
    float sS = sqrtf(fmaxf(e0, 1e-6f));
    float den = fmaxf(sL, sS) + 1e-6f;
    out[OFF_AX + pt * 2 + 0] = fmaxf(sL / den, 0.2f);
    out[OFF_AX + pt * 2 + 1] = fmaxf(sS / den, 0.2f);

    float* lp = g_lcc + (size_t)pt * 10;
    #pragma unroll
    for (int k = 0; k < 5; ++k) {
        lp[2*k]   = __fmaf_rn(cy[k], v10, __fmul_rn(cx[k], v00));
        lp[2*k+1] = __fmaf_rn(cy[k], v11, __fmul_rn(cx[k], v01));
    }
}

// ---------------- Kernel B: local MLP 2->64->128->64 + max over K ----------------
// 32 points/CTA (160 rows), 512 threads. Weight loads warp-uniform LDS.128.
#define B_SMEM_FLOATS (27392 + 160*133)
__global__ __launch_bounds__(512)
void local_mlp_kernel(const float* __restrict__ lw1, const float* __restrict__ lb1,
                      const float* __restrict__ lw2, const float* __restrict__ lb2,
                      const float* __restrict__ lw3, const float* __restrict__ lb3)
{
    extern __shared__ float smf[];
    float* w1s  = smf;
    float* b1s  = smf + 128;
    float* w2s  = smf + 192;
    float* b2s  = smf + 8384;
    float* w3s  = smf + 8512;
    float* b3s  = smf + 16704;
    float* lccs = smf + 16768;
    float* h1T  = smf + 17088;   // [64][161]  k-major
    float* h2s  = smf + 27392;   // [160][133]

    const int tid  = threadIdx.x;
    const int base = blockIdx.x * 32;

    for (int i = tid; i < 128;  i += 512) { w1s[i] = lw1[i]; b2s[i] = lb2[i]; }
    for (int i = tid; i < 64;   i += 512) { b1s[i] = lb1[i]; b3s[i] = lb3[i]; }
    for (int i = tid; i < 8192; i += 512) { w2s[i] = lw2[i]; w3s[i] = lw3[i]; }
    if (tid < 320) lccs[tid] = g_lcc[(size_t)base * 10 + tid];
    __syncthreads();

    // stage 1: h1 (160x64) -> h1T[c*161 + r]
    for (int idx = tid; idx < 160 * 64; idx += 512) {
        int r = idx >> 6, c = idx & 63;
        float v = fmaf(lccs[2*r], w1s[c], fmaf(lccs[2*r+1], w1s[64 + c], b1s[c]));
        h1T[c * 161 + r] = fmaxf(v, 0.f);
    }
    __syncthreads();

    const int rg = tid & 31;       // point
    const int cg = tid >> 5;       // 0..15
    const int r0 = rg * 5;

    // stage 2: h2 (160x128), tile 5 rows x 8 cols, weights warp-uniform
    {
        const int c0 = cg * 8;
        ull acc[5][4];
        ulonglong2 bp0 = *reinterpret_cast<const ulonglong2*>(b2s + c0);
        ulonglong2 bp1 = *reinterpret_cast<const ulonglong2*>(b2s + c0 + 4);
        #pragma unroll
        for (int j = 0; j < 5; ++j) {
            acc[j][0] = bp0.x; acc[j][1] = bp0.y; acc[j][2] = bp1.x; acc[j][3] = bp1.y;
        }
        #pragma unroll 2
        for (int k = 0; k < 64; ++k) {
            ull av[5];
            #pragma unroll
            for (int j = 0; j < 5; ++j) av[j] = pack2(h1T[k * 161 + r0 + j]);
            ulonglong2 w0 = *reinterpret_cast<const ulonglong2*>(w2s + k*128 + c0);
            ulonglong2 w1 = *reinterpret_cast<const ulonglong2*>(w2s + k*128 + c0 + 4);
            #pragma unroll
            for (int j = 0; j < 5; ++j) {
                ffma2(acc[j][0], av[j], w0.x);
                ffma2(acc[j][1], av[j], w0.y);
                ffma2(acc[j][2], av[j], w1.x);
                ffma2(acc[j][3], av[j], w1.y);
            }
        }
        #pragma unroll
        for (int j = 0; j < 5; ++j) {
            float* hp = h2s + (r0 + j) * 133 + c0;
            #pragma unroll
            for (int i = 0; i < 4; ++i) {
                hp[2*i]   = fmaxf(lo2(acc[j][i]), 0.f);
                hp[2*i+1] = fmaxf(hi2(acc[j][i]), 0.f);
            }
        }
    }
    __syncthreads();

    // stage 3: h3 (160x64), tile 5 rows x 4 cols, fused relu+max over 5 neighbors
    {
        const int c0 = cg * 4;
        ull acc3[5][2];
        ulonglong2 bp = *reinterpret_cast<const ulonglong2*>(b3s + c0);
        #pragma unroll
        for (int j = 0; j < 5; ++j) { acc3[j][0] = bp.x; acc3[j][1] = bp.y; }
        #pragma unroll 2
        for (int k = 0; k < 128; ++k) {
            ull av[5];
            #pragma unroll
            for (int j = 0; j < 5; ++j) av[j] = pack2(h2s[(r0 + j) * 133 + k]);
            ulonglong2 w = *reinterpret_cast<const ulonglong2*>(w3s + k*64 + c0);
            #pragma unroll
            for (int j = 0; j < 5; ++j) {
                ffma2(acc3[j][0], av[j], w.x);
                ffma2(acc3[j][1], av[j], w.y);
            }
        }
        float4 o;
        float m0 = 0.f, m1 = 0.f, m2 = 0.f, m3 = 0.f;   // relu floor
        #pragma unroll
        for (int j = 0; j < 5; ++j) {
            m0 = fmaxf(m0, lo2(acc3[j][0]));
            m1 = fmaxf(m1, hi2(acc3[j][0]));
            m2 = fmaxf(m2, lo2(acc3[j][1]));
            m3 = fmaxf(m3, hi2(acc3[j][1]));
        }
        o.x = m0; o.y = m1; o.z = m2; o.w = m3;
        *reinterpret_cast<float4*>(g_lf + (size_t)(base + rg) * 64 + c0) = o;
    }
}

// ---------------- Kernel C: BOTH heads, compile-time dims per branch ----------------
template<int INDIM>
__device__ __forceinline__ void head_body(
    const float* __restrict__ w1s, const float* __restrict__ b1s,
    const float* __restrict__ w2s, const float* __restrict__ b2s,
    const float* __restrict__ ins, float* __restrict__ hs,
    float* __restrict__ outp, int base, int tid)
{
    const int p  = tid & 63;
    const int c0 = (tid >> 6) * 16;   // warp-uniform column base

    // stage 1: 64 x 128, tile 1 row x 16 cols
    {
        ull acc[8];
        ulonglong2 bq0 = *reinterpret_cast<const ulonglong2*>(b1s + c0);
        ulonglong2 bq1 = *reinterpret_cast<const ulonglong2*>(b1s + c0 + 4);
        ulonglong2 bq2 = *reinterpret_cast<const ulonglong2*>(b1s + c0 + 8);
        ulonglong2 bq3 = *reinterpret_cast<const ulonglong2*>(b1s + c0 + 12);
        acc[0]=bq0.x; acc[1]=bq0.y; acc[2]=bq1.x; acc[3]=bq1.y;
        acc[4]=bq2.x; acc[5]=bq2.y; acc[6]=bq3.x; acc[7]=bq3.y;
        #pragma unroll 2
        for (int k = 0; k < INDIM; ++k) {
            ull a = pack2(ins[p * 67 + k]);
            const float* wr = w1s + k * 128 + c0;
            ulonglong2 w0 = *reinterpret_cast<const ulonglong2*>(wr);
            ulonglong2 w1q = *reinterpret_cast<const ulonglong2*>(wr + 4);
            ulonglong2 w2q = *reinterpret_cast<const ulonglong2*>(wr + 8);
            ulonglong2 w3q = *reinterpret_cast<const ulonglong2*>(wr + 12);
            ffma2(acc[0], a, w0.x); ffma2(acc[1], a, w0.y);
            ffma2(acc[2], a, w1q.x); ffma2(acc[3], a, w1q.y);
            ffma2(acc[4], a, w2q.x); ffma2(acc[5], a, w2q.y);
            ffma2(acc[6], a, w3q.x); ffma2(acc[7], a, w3q.y);
        }
        float* hp = hs + p * 131 + c0;
        #pragma unroll
        for (int i = 0; i < 8; ++i) {
            hp[2*i]   = fmaxf(lo2(acc[i]), 0.f);
            hp[2*i+1] = fmaxf(hi2(acc[i]), 0.f);
        }
    }
    __syncthreads();

    // stage 2: 64 x 128
    {
        ull acc[8];
        ulonglong2 bq0 = *reinterpret_cast<const ulonglong2*>(b2s + c0);
        ulonglong2 bq1 = *reinterpret_cast<const ulonglong2*>(b2s + c0 + 4);
        ulonglong2 bq2 = *reinterpret_cast<const ulonglong2*>(b2s + c0 + 8);
        ulonglong2 bq3 = *reinterpret_cast<const ulonglong2*>(b2s + c0 + 12);
        acc[0]=bq0.x; acc[1]=bq0.y; acc[2]=bq1.x; acc[3]=bq1.y;
        acc[4]=bq2.x; acc[5]=bq2.y; acc[6]=bq3.x; acc[7]=bq3.y;
        #pragma unroll 4
        for (int k = 0; k < 128; ++k) {
            ull a = pack2(hs[p * 131 + k]);
            const float* wr = w2s + k * 128 + c0;
            ulonglong2 w0 = *reinterpret_cast<const ulonglong2*>(wr);
            ulonglong2 w1q = *reinterpret_cast<const ulonglong2*>(wr + 4);
            ulonglong2 w2q = *reinterpret_cast<const ulonglong2*>(wr + 8);
            ulonglong2 w3q = *reinterpret_cast<const ulonglong2*>(wr + 12);
            ffma2(acc[0], a, w0.x); ffma2(acc[1], a, w0.y);
            ffma2(acc[2], a, w1q.x); ffma2(acc[3], a, w1q.y);
            ffma2(acc[4], a, w2q.x); ffma2(acc[5], a, w2q.y);
            ffma2(acc[6], a, w3q.x); ffma2(acc[7], a, w3q.y);
        }
        float* op = outp + (size_t)(base + p) * 128 + c0;
        #pragma unroll
        for (int i = 0; i < 8; ++i) {
            float2 v = make_float2(fmaxf(lo2(acc[i]), 0.f), fmaxf(hi2(acc[i]), 0.f));
            *reinterpret_cast<float2*>(op + 2*i) = v;
        }
    }
}

#define H_SMEM_FLOATS (29376 + 64*131)
__global__ __launch_bounds__(512)
void head2_kernel(const float* __restrict__ xg,
                  const float* __restrict__ cw1, const float* __restrict__ cb1,
                  const float* __restrict__ cw2, const float* __restrict__ cb2,
                  const float* __restrict__ tw1, const float* __restrict__ tb1,
                  const float* __restrict__ tw2, const float* __restrict__ tb2,
                  float* __restrict__ outg)
{
    extern __shared__ float smf[];
    float* w1s = smf;
    float* b1s = smf + 8448;
    float* w2s = smf + 8576;
    float* b2s = smf + 24960;
    float* ins = smf + 25088;   // [64][67]
    float* hs  = smf + 29376;   // [64][131]

    const int head = blockIdx.y;
    const float* w1 = head ? tw1 : cw1;
    const float* b1 = head ? tb1 : cb1;
    const float* w2 = head ? tw2 : cw2;
    const float* b2 = head ? tb2 : cb2;
    const int indim = head ? 64 : 66;
    const int xoff  = head ? 0 : 2;
    float* outp = outg + (head ? OFF_TOPO : 0);

    const int tid  = threadIdx.x;
    const int base = blockIdx.x * 64;

    for (int i = tid; i < indim * 128; i += 512) w1s[i] = w1[i];
    for (int i = tid; i < 16384;       i += 512) w2s[i] = w2[i];
    if (tid < 128) { b1s[tid] = b1[tid]; b2s[tid] = b2[tid]; }
    for (int idx = tid; idx < 64 * 64; idx += 512) {
        int p = idx >> 6, c = idx & 63;
        ins[p * 67 + xoff + c] = g_lf[(size_t)(base + p) * 64 + c];
    }
    if (!head && tid < 128) {
        int p = tid >> 1, c = tid & 1;
        ins[p * 67 + c] = xg[(size_t)(base + p) * 2 + c];
    }
    __syncthreads();

    if (head) head_body<64>(w1s, b1s, w2s, b2s, ins, hs, outp, base, tid);
    else      head_body<66>(w1s, b1s, w2s, b2s, ins, hs, outp, base, tid);
}

// ---------------- launch ----------------
extern "C" void kernel_launch(void* const* d_in, const int* in_sizes, int n_in,
                              void* d_out, int out_size)
{
    (void)in_sizes; (void)n_in; (void)out_size;
    const float* x   = (const float*)d_in[0];
    const float* lw1 = (const float*)d_in[1];
    const float* lb1 = (const float*)d_in[2];
    const float* lw2 = (const float*)d_in[3];
    const float* lb2 = (const float*)d_in[4];
    const float* lw3 = (const float*)d_in[5];
    const float* lb3 = (const float*)d_in[6];
    const float* cw1 = (const float*)d_in[7];
    const float* cb1 = (const float*)d_in[8];
    const float* cw2 = (const float*)d_in[9];
    const float* cb2 = (const float*)d_in[10];
    const float* tw1 = (const float*)d_in[11];
    const float* tb1 = (const float*)d_in[12];
    const float* tw2 = (const float*)d_in[13];
    const float* tb2 = (const float*)d_in[14];
    float* out = (float*)d_out;

    const int smB = B_SMEM_FLOATS * 4;
    const int smH = H_SMEM_FLOATS * 4;
    cudaFuncSetAttribute(local_mlp_kernel, cudaFuncAttributeMaxDynamicSharedMemorySize, smB);
    cudaFuncSetAttribute(head2_kernel,     cudaFuncAttributeMaxDynamicSharedMemorySize, smH);

    knn_part_kernel<<<dim3(NN/128, SLICES, 8), 128>>>(x);
    knn_merge_geom_kernel<<<NPTS/128, 128>>>(x, out);
    local_mlp_kernel<<<NPTS/32, 512, smB>>>(lw1, lb1, lw2, lb2, lw3, lb3);
    head2_kernel<<<dim3(NPTS/64, 2), 512, smH>>>(x, cw1, cb1, cw2, cb2,
                                                 tw1, tb1, tw2, tb2, out);
}

// round 12
// speedup vs baseline: 1.9895x; 1.0400x over previous
#include <cuda_runtime.h>
#include <math.h>

#define NN 4096
#define NPTS 32768
#define SLICES 4
#define SLICE_N 1024

typedef unsigned long long ull;

__device__ __forceinline__ ull pack2(float v) {
    ull r; unsigned u = __float_as_uint(v);
    asm("mov.b64 %0,{%1,%1};" : "=l"(r) : "r"(u));
    return r;
}
__device__ __forceinline__ ull pack2f(float lo, float hi) {
    ull r;
    asm("mov.b64 %0,{%1,%2};" : "=l"(r) : "r"(__float_as_uint(lo)), "r"(__float_as_uint(hi)));
    return r;
}
__device__ __forceinline__ void ffma2(ull &d, ull a, ull b) {
    asm("fma.rn.f32x2 %0, %1, %2, %0;" : "+l"(d) : "l"(a), "l"(b));
}
__device__ __forceinline__ ull mul2(ull a, ull b) {
    ull r; asm("mul.rn.f32x2 %0, %1, %2;" : "=l"(r) : "l"(a), "l"(b)); return r;
}
__device__ __forceinline__ ull add2(ull a, ull b) {
    ull r; asm("add.rn.f32x2 %0, %1, %2;" : "=l"(r) : "l"(a), "l"(b)); return r;
}
__device__ __forceinline__ ull fma2v(ull a, ull b, ull c) {
    ull r; asm("fma.rn.f32x2 %0, %1, %2, %3;" : "=l"(r) : "l"(a), "l"(b), "l"(c)); return r;
}
__device__ __forceinline__ float lo2(ull v) { return __uint_as_float((unsigned)v); }
__device__ __forceinline__ float hi2(ull v) { return __uint_as_float((unsigned)(v >> 32)); }

// scratch (static __device__, no allocation)
__device__ float g_lcc[NPTS * 10];        // (pt, k, xy)
__device__ float g_lf [NPTS * 64];        // local_feats
__device__ float g_pd [NPTS * 20];        // partial top-5 dists, 4 slices
__device__ int   g_pi [NPTS * 20];        // partial top-5 indices

// out layout: [cls 32768*128 | topo 32768*128 | angle 32768 | axes 32768*2]
#define OFF_TOPO 4194304
#define OFF_ANG  8388608
#define OFF_AX   8421376

// insert (dd, mi) into sorted-ascending register top-5 with strict < (stable by index)
#define INS5(dd, mi)                                                        \
    if (dd < d4) {                                                          \
        if (dd < d3) {                                                      \
            d4 = d3; i4 = i3;                                               \
            if (dd < d2) {                                                  \
                d3 = d2; i3 = i2;                                           \
                if (dd < d1) {                                              \
                    d2 = d1; i2 = i1;                                       \
                    if (dd < d0) { d1 = d0; i1 = i0; d0 = dd; i0 = mi; }    \
                    else          { d1 = dd; i1 = mi; }                     \
                } else { d2 = dd; i2 = mi; }                                \
            } else { d3 = dd; i3 = mi; }                                    \
        } else { d4 = dd; i4 = mi; }                                        \
    }

// ---------------- Kernel A1: partial KNN over one candidate slice (packed f32x2) ----------------
__global__ __launch_bounds__(128)
void knn_part_kernel(const float* __restrict__ xg)
{
    __shared__ ull sx[SLICE_N / 2];   // packed x pairs
    __shared__ ull sy[SLICE_N / 2];   // packed y pairs
    __shared__ ull sq[SLICE_N / 2];   // packed sq pairs

    const int b  = blockIdx.z;
    const int s  = blockIdx.y;
    const int m0 = s * SLICE_N;
    const float2* xb = reinterpret_cast<const float2*>(xg) + (size_t)b * NN;

    for (int i = threadIdx.x; i < SLICE_N / 2; i += 128) {
        float2 p0 = xb[m0 + 2*i];
        float2 p1 = xb[m0 + 2*i + 1];
        sx[i] = pack2f(p0.x, p1.x);
        sy[i] = pack2f(p0.y, p1.y);
        // sq = rn(x*x) + rn(y*y)  (jnp.sum(x*x,-1), no fma)
        float q0 = __fadd_rn(__fmul_rn(p0.x, p0.x), __fmul_rn(p0.y, p0.y));
        float q1 = __fadd_rn(__fmul_rn(p1.x, p1.x), __fmul_rn(p1.y, p1.y));
        sq[i] = pack2f(q0, q1);
    }
    __syncthreads();

    const int n = blockIdx.x * 128 + threadIdx.x;
    float2 qv = xb[n];
    const float sqn = __fadd_rn(__fmul_rn(qv.x, qv.x), __fmul_rn(qv.y, qv.y));
    const ull QX = pack2(qv.x), QY = pack2(qv.y), SQN = pack2(sqn), NEG2 = pack2(-2.0f);

    float d0 = 3.4e38f, d1 = 3.4e38f, d2 = 3.4e38f, d3 = 3.4e38f, d4 = 3.4e38f;
    int   i0 = 0, i1 = 0, i2 = 0, i3 = 0, i4 = 0;

    #pragma unroll 4
    for (int j = 0; j < SLICE_N / 2; ++j) {
        ull X = sx[j], Y = sy[j], S = sq[j];
        // dot = fma(y, qy, rn(x*qx))  (Eigen k=2 fold), dd = rn(sum - 2*dot)
        ull dot = fma2v(Y, QY, mul2(X, QX));
        ull sum = add2(SQN, S);
        ull ddp = fma2v(dot, NEG2, sum);   // exact: 2*dot has no rounding
        float ddlo = lo2(ddp), ddhi = hi2(ddp);
        int mi = m0 + 2*j;
        INS5(ddlo, mi);
        INS5(ddhi, mi + 1);
    }

    float* pd = g_pd + ((size_t)(b * NN + n)) * 20 + s * 5;
    int*   pi = g_pi + ((size_t)(b * NN + n)) * 20 + s * 5;
    pd[0] = d0; pd[1] = d1; pd[2] = d2; pd[3] = d3; pd[4] = d4;
    pi[0] = i0; pi[1] = i1; pi[2] = i2; pi[3] = i3; pi[4] = i4;
}

// ---------------- Kernel A2: merge partials + slaev2 eigh + lcc ----------------
__global__ __launch_bounds__(128)
void knn_merge_geom_kernel(const float* __restrict__ xg, float* __restrict__ out)
{
    const int pt = blockIdx.x * 128 + threadIdx.x;
    const int b  = pt >> 12;
    const int n  = pt & (NN - 1);
    const float2* xb = reinterpret_cast<const float2*>(xg) + (size_t)b * NN;

    float pd[20]; int pi[20];
    {
        const float* gp = g_pd + (size_t)pt * 20;
        const int*   gi = g_pi + (size_t)pt * 20;
        #pragma unroll
        for (int j = 0; j < 20; ++j) { pd[j] = gp[j]; pi[j] = gi[j]; }
    }

    // exact global top-5 by (d, idx) lexicographic (== lax.top_k stable order)
    int nb[5];
    unsigned used = 0;
    #pragma unroll
    for (int k = 0; k < 5; ++k) {
        float best = 3.5e38f; int bidx = 0x7fffffff; int bj = 0;
        #pragma unroll
        for (int j = 0; j < 20; ++j) {
            bool freej = !((used >> j) & 1u);
            float dj = pd[j]; int ij = pi[j];
            if (freej && (dj < best || (dj == best && ij < bidx))) {
                best = dj; bidx = ij; bj = j;
            }
        }
        used |= 1u << bj;
        nb[k] = bidx;
    }

    const float qx = xb[n].x, qy = xb[n].y;
    float rx[5], ry[5];
    #pragma unroll
    for (int k = 0; k < 5; ++k) {
        float2 p = xb[nb[k]];
        rx[k] = __fsub_rn(p.x, qx);
        ry[k] = __fsub_rn(p.y, qy);
    }
    float sxs = __fadd_rn(__fadd_rn(__fadd_rn(__fadd_rn(rx[0], rx[1]), rx[2]), rx[3]), rx[4]);
    float sys = __fadd_rn(__fadd_rn(__fadd_rn(__fadd_rn(ry[0], ry[1]), ry[2]), ry[3]), ry[4]);
    float mx = __fdiv_rn(sxs, 5.0f);
    float my = __fdiv_rn(sys, 5.0f);
    float cx[5], cy[5];
    float sxx = 0.f, sxy = 0.f, syy = 0.f;
    #pragma unroll
    for (int k = 0; k < 5; ++k) {
        cx[k] = __fsub_rn(rx[k], mx);
        cy[k] = __fsub_rn(ry[k], my);
        sxx = __fmaf_rn(cx[k], cx[k], sxx);
        sxy = __fmaf_rn(cx[k], cy[k], sxy);
        syy = __fmaf_rn(cy[k], cy[k], syy);
    }
    float a  = __fadd_rn(__fmul_rn(sxx, 0.25f), 1e-6f);
    float bv = __fmul_rn(sxy, 0.25f);
    float c  = __fadd_rn(__fmul_rn(syy, 0.25f), 1e-6f);

    // ---- LAPACK slaev2 (a,c > 0 => sm > 0 => sgn1 = +1) ----
    float smv = a + c, df = a - c;
    float adf = fabsf(df);
    float tb  = bv + bv;
    float ab  = fabsf(tb);
    float rt;
    if (adf > ab)      { float t = ab / adf; rt = adf * sqrtf(1.f + t*t); }
    else if (adf < ab) { float t = adf / ab; rt = ab * sqrtf(1.f + t*t); }
    else               { rt = ab * 1.4142135623730951f; }
    float rt1 = 0.5f * (smv + rt);
    float acmx, acmn;
    if (fabsf(a) > fabsf(c)) { acmx = a; acmn = c; } else { acmx = c; acmn = a; }
    float rt2 = (acmx / rt1) * acmn - (bv / rt1) * bv;
    float cs; int sgn2;
    if (df >= 0.f) { cs = df + rt; sgn2 = 1; }
    else           { cs = df - rt; sgn2 = -1; }
    float acs = fabsf(cs), cs1, sn1;
    if (acs > ab)       { float ct = -tb / cs; sn1 = 1.f / sqrtf(1.f + ct*ct); cs1 = ct * sn1; }
    else if (ab == 0.f) { cs1 = 1.f; sn1 = 0.f; }
    else                { float tn = -cs / tb; cs1 = 1.f / sqrtf(1.f + tn*tn); sn1 = tn * cs1; }
    if (sgn2 == 1)      { float t = cs1; cs1 = -sn1; sn1 = t; }

    float e0, e1, v00, v10, v01, v11;
    if (rt2 < rt1) { e0 = rt2; e1 = rt1; v00 = -sn1; v10 = cs1; v01 = cs1;  v11 = sn1; }
    else           { e0 = rt1; e1 = rt2; v00 = cs1;  v10 = sn1; v01 = -sn1; v11 = cs1; }

    out[OFF_ANG + pt] = atan2f(v11, v01);
    float sL = sqrtf(fmaxf(e1, 1e-6f));
    float sS = sqrtf(fmaxf(e0, 1e-6f));
    float den = fmaxf(sL, sS) + 1e-6f;
    out[OFF_AX + pt * 2 + 0] = fmaxf(sL / den, 0.2f);
    out[OFF_AX + pt * 2 + 1] = fmaxf(sS / den, 0.2f);

    float* lp = g_lcc + (size_t)pt * 10;
    #pragma unroll
    for (int k = 0; k < 5; ++k) {
        lp[2*k]   = __fmaf_rn(cy[k], v10, __fmul_rn(cx[k], v00));
        lp[2*k+1] = __fmaf_rn(cy[k], v11, __fmul_rn(cx[k], v01));
    }
}

// ---------------- Kernel B: local MLP 2->64->128->64 + max over K ----------------
// 32 points/CTA (160 rows), 512 threads. Weight loads warp-uniform LDS.128.
#define B_SMEM_FLOATS (27392 + 160*133)
__global__ __launch_bounds__(512)
void local_mlp_kernel(const float* __restrict__ lw1, const float* __restrict__ lb1,
                      const float* __restrict__ lw2, const float* __restrict__ lb2,
                      const float* __restrict__ lw3, const float* __restrict__ lb3)
{
    extern __shared__ float smf[];
    float* w1s  = smf;
    float* b1s  = smf + 128;
    float* w2s  = smf + 192;
    float* b2s  = smf + 8384;
    float* w3s  = smf + 8512;
    float* b3s  = smf + 16704;
    float* lccs = smf + 16768;
    float* h1T  = smf + 17088;   // [64][161]  k-major
    float* h2s  = smf + 27392;   // [160][133]

    const int tid  = threadIdx.x;
    const int base = blockIdx.x * 32;

    for (int i = tid; i < 128;  i += 512) { w1s[i] = lw1[i]; b2s[i] = lb2[i]; }
    for (int i = tid; i < 64;   i += 512) { b1s[i] = lb1[i]; b3s[i] = lb3[i]; }
    for (int i = tid; i < 8192; i += 512) { w2s[i] = lw2[i]; w3s[i] = lw3[i]; }
    if (tid < 320) lccs[tid] = g_lcc[(size_t)base * 10 + tid];
    __syncthreads();

    // stage 1: h1 (160x64) -> h1T[c*161 + r]
    for (int idx = tid; idx < 160 * 64; idx += 512) {
        int r = idx >> 6, c = idx & 63;
        float v = fmaf(lccs[2*r], w1s[c], fmaf(lccs[2*r+1], w1s[64 + c], b1s[c]));
        h1T[c * 161 + r] = fmaxf(v, 0.f);
    }
    __syncthreads();

    const int rg = tid & 31;       // point
    const int cg = tid >> 5;       // 0..15
    const int r0 = rg * 5;

    // stage 2: h2 (160x128), tile 5 rows x 8 cols, weights warp-uniform
    {
        const int c0 = cg * 8;
        ull acc[5][4];
        ulonglong2 bp0 = *reinterpret_cast<const ulonglong2*>(b2s + c0);
        ulonglong2 bp1 = *reinterpret_cast<const ulonglong2*>(b2s + c0 + 4);
        #pragma unroll
        for (int j = 0; j < 5; ++j) {
            acc[j][0] = bp0.x; acc[j][1] = bp0.y; acc[j][2] = bp1.x; acc[j][3] = bp1.y;
        }
        #pragma unroll 2
        for (int k = 0; k < 64; ++k) {
            ull av[5];
            #pragma unroll
            for (int j = 0; j < 5; ++j) av[j] = pack2(h1T[k * 161 + r0 + j]);
            ulonglong2 w0 = *reinterpret_cast<const ulonglong2*>(w2s + k*128 + c0);
            ulonglong2 w1 = *reinterpret_cast<const ulonglong2*>(w2s + k*128 + c0 + 4);
            #pragma unroll
            for (int j = 0; j < 5; ++j) {
                ffma2(acc[j][0], av[j], w0.x);
                ffma2(acc[j][1], av[j], w0.y);
                ffma2(acc[j][2], av[j], w1.x);
                ffma2(acc[j][3], av[j], w1.y);
            }
        }
        #pragma unroll
        for (int j = 0; j < 5; ++j) {
            float* hp = h2s + (r0 + j) * 133 + c0;
            #pragma unroll
            for (int i = 0; i < 4; ++i) {
                hp[2*i]   = fmaxf(lo2(acc[j][i]), 0.f);
                hp[2*i+1] = fmaxf(hi2(acc[j][i]), 0.f);
            }
        }
    }
    __syncthreads();

    // stage 3: h3 (160x64), tile 5 rows x 4 cols, fused relu+max over 5 neighbors
    {
        const int c0 = cg * 4;
        ull acc3[5][2];
        ulonglong2 bp = *reinterpret_cast<const ulonglong2*>(b3s + c0);
        #pragma unroll
        for (int j = 0; j < 5; ++j) { acc3[j][0] = bp.x; acc3[j][1] = bp.y; }
        #pragma unroll 2
        for (int k = 0; k < 128; ++k) {
            ull av[5];
            #pragma unroll
            for (int j = 0; j < 5; ++j) av[j] = pack2(h2s[(r0 + j) * 133 + k]);
            ulonglong2 w = *reinterpret_cast<const ulonglong2*>(w3s + k*64 + c0);
            #pragma unroll
            for (int j = 0; j < 5; ++j) {
                ffma2(acc3[j][0], av[j], w.x);
                ffma2(acc3[j][1], av[j], w.y);
            }
        }
        float4 o;
        float m0 = 0.f, m1 = 0.f, m2 = 0.f, m3 = 0.f;   // relu floor
        #pragma unroll
        for (int j = 0; j < 5; ++j) {
            m0 = fmaxf(m0, lo2(acc3[j][0]));
            m1 = fmaxf(m1, hi2(acc3[j][0]));
            m2 = fmaxf(m2, lo2(acc3[j][1]));
            m3 = fmaxf(m3, hi2(acc3[j][1]));
        }
        o.x = m0; o.y = m1; o.z = m2; o.w = m3;
        *reinterpret_cast<float4*>(g_lf + (size_t)(base + rg) * 64 + c0) = o;
    }
}

// ---------------- Kernel C: BOTH heads, 128 points/CTA, 512 threads ----------------
// thread tile: 2 points (p, p+64) x 16 cols; weight LDS warp-uniform broadcast.
template<int INDIM>
__device__ __forceinline__ void head_body(
    const float* __restrict__ w1s, const float* __restrict__ b1s,
    const float* __restrict__ w2s, const float* __restrict__ b2s,
    const float* __restrict__ ins, float* __restrict__ hs,
    float* __restrict__ outp, int base, int tid)
{
    const int p  = tid & 63;          // points p and p+64
    const int c0 = (tid >> 6) * 16;   // warp-uniform column base

    // stage 1: 128 x 128, tile 2 rows x 16 cols
    {
        ull acc0[8], acc1[8];
        ulonglong2 bq0 = *reinterpret_cast<const ulonglong2*>(b1s + c0);
        ulonglong2 bq1 = *reinterpret_cast<const ulonglong2*>(b1s + c0 + 4);
        ulonglong2 bq2 = *reinterpret_cast<const ulonglong2*>(b1s + c0 + 8);
        ulonglong2 bq3 = *reinterpret_cast<const ulonglong2*>(b1s + c0 + 12);
        acc0[0]=bq0.x; acc0[1]=bq0.y; acc0[2]=bq1.x; acc0[3]=bq1.y;
        acc0[4]=bq2.x; acc0[5]=bq2.y; acc0[6]=bq3.x; acc0[7]=bq3.y;
        #pragma unroll
        for (int i = 0; i < 8; ++i) acc1[i] = acc0[i];
        #pragma unroll 2
        for (int k = 0; k < INDIM; ++k) {
            ull a0 = pack2(ins[p * 67 + k]);
            ull a1 = pack2(ins[(p + 64) * 67 + k]);
            const float* wr = w1s + k * 128 + c0;
            ulonglong2 w0 = *reinterpret_cast<const ulonglong2*>(wr);
            ulonglong2 w1q = *reinterpret_cast<const ulonglong2*>(wr + 4);
            ulonglong2 w2q = *reinterpret_cast<const ulonglong2*>(wr + 8);
            ulonglong2 w3q = *reinterpret_cast<const ulonglong2*>(wr + 12);
            ffma2(acc0[0], a0, w0.x);  ffma2(acc1[0], a1, w0.x);
            ffma2(acc0[1], a0, w0.y);  ffma2(acc1[1], a1, w0.y);
            ffma2(acc0[2], a0, w1q.x); ffma2(acc1[2], a1, w1q.x);
            ffma2(acc0[3], a0, w1q.y); ffma2(acc1[3], a1, w1q.y);
            ffma2(acc0[4], a0, w2q.x); ffma2(acc1[4], a1, w2q.x);
            ffma2(acc0[5], a0, w2q.y); ffma2(acc1[5], a1, w2q.y);
            ffma2(acc0[6], a0, w3q.x); ffma2(acc1[6], a1, w3q.x);
            ffma2(acc0[7], a0, w3q.y); ffma2(acc1[7], a1, w3q.y);
        }
        float* hp0 = hs + p * 131 + c0;
        float* hp1 = hs + (p + 64) * 131 + c0;
        #pragma unroll
        for (int i = 0; i < 8; ++i) {
            hp0[2*i]   = fmaxf(lo2(acc0[i]), 0.f);
            hp0[2*i+1] = fmaxf(hi2(acc0[i]), 0.f);
            hp1[2*i]   = fmaxf(lo2(acc1[i]), 0.f);
            hp1[2*i+1] = fmaxf(hi2(acc1[i]), 0.f);
        }
    }
    __syncthreads();

    // stage 2: 128 x 128
    {
        ull acc0[8], acc1[8];
        ulonglong2 bq0 = *reinterpret_cast<const ulonglong2*>(b2s + c0);
        ulonglong2 bq1 = *reinterpret_cast<const ulonglong2*>(b2s + c0 + 4);
        ulonglong2 bq2 = *reinterpret_cast<const ulonglong2*>(b2s + c0 + 8);
        ulonglong2 bq3 = *reinterpret_cast<const ulonglong2*>(b2s + c0 + 12);
        acc0[0]=bq0.x; acc0[1]=bq0.y; acc0[2]=bq1.x; acc0[3]=bq1.y;
        acc0[4]=bq2.x; acc0[5]=bq2.y; acc0[6]=bq3.x; acc0[7]=bq3.y;
        #pragma unroll
        for (int i = 0; i < 8; ++i) acc1[i] = acc0[i];
        #pragma unroll 2
        for (int k = 0; k < 128; ++k) {
            ull a0 = pack2(hs[p * 131 + k]);
            ull a1 = pack2(hs[(p + 64) * 131 + k]);
            const float* wr = w2s + k * 128 + c0;
            ulonglong2 w0 = *reinterpret_cast<const ulonglong2*>(wr);
            ulonglong2 w1q = *reinterpret_cast<const ulonglong2*>(wr + 4);
            ulonglong2 w2q = *reinterpret_cast<const ulonglong2*>(wr + 8);
            ulonglong2 w3q = *reinterpret_cast<const ulonglong2*>(wr + 12);
            ffma2(acc0[0], a0, w0.x);  ffma2(acc1[0], a1, w0.x);
            ffma2(acc0[1], a0, w0.y);  ffma2(acc1[1], a1, w0.y);
            ffma2(acc0[2], a0, w1q.x); ffma2(acc1[2], a1, w1q.x);
            ffma2(acc0[3], a0, w1q.y); ffma2(acc1[3], a1, w1q.y);
            ffma2(acc0[4], a0, w2q.x); ffma2(acc1[4], a1, w2q.x);
            ffma2(acc0[5], a0, w2q.y); ffma2(acc1[5], a1, w2q.y);
            ffma2(acc0[6], a0, w3q.x); ffma2(acc1[6], a1, w3q.x);
            ffma2(acc0[7], a0, w3q.y); ffma2(acc1[7], a1, w3q.y);
        }
        float* op0 = outp + (size_t)(base + p) * 128 + c0;
        float* op1 = outp + (size_t)(base + p + 64) * 128 + c0;
        #pragma unroll
        for (int i = 0; i < 8; ++i) {
            float2 v0 = make_float2(fmaxf(lo2(acc0[i]), 0.f), fmaxf(hi2(acc0[i]), 0.f));
            float2 v1 = make_float2(fmaxf(lo2(acc1[i]), 0.f), fmaxf(hi2(acc1[i]), 0.f));
            *reinterpret_cast<float2*>(op0 + 2*i) = v0;
            *reinterpret_cast<float2*>(op1 + 2*i) = v1;
        }
    }
}

// smem: w1s 8448 | b1s 128 | w2s 16384 | b2s 128 | ins 128*67 | hs 128*131
#define H_SMEM_FLOATS (8448 + 128 + 16384 + 128 + 128*67 + 128*131)
__global__ __launch_bounds__(512)
void head2_kernel(const float* __restrict__ xg,
                  const float* __restrict__ cw1, const float* __restrict__ cb1,
                  const float* __restrict__ cw2, const float* __restrict__ cb2,
                  const float* __restrict__ tw1, const float* __restrict__ tb1,
                  const float* __restrict__ tw2, const float* __restrict__ tb2,
                  float* __restrict__ outg)
{
    extern __shared__ float smf[];
    float* w1s = smf;
    float* b1s = smf + 8448;
    float* w2s = smf + 8576;
    float* b2s = smf + 24960;
    float* ins = smf + 25088;   // [128][67]
    float* hs  = smf + 33664;   // [128][131]

    const int head = blockIdx.y;
    const float* w1 = head ? tw1 : cw1;
    const float* b1 = head ? tb1 : cb1;
    const float* w2 = head ? tw2 : cw2;
    const float* b2 = head ? tb2 : cb2;
    const int indim = head ? 64 : 66;
    const int xoff  = head ? 0 : 2;
    float* outp = outg + (head ? OFF_TOPO : 0);

    const int tid  = threadIdx.x;
    const int base = blockIdx.x * 128;

    for (int i = tid; i < indim * 128; i += 512) w1s[i] = w1[i];
    for (int i = tid; i < 16384;       i += 512) w2s[i] = w2[i];
    if (tid < 128) { b1s[tid] = b1[tid]; b2s[tid] = b2[tid]; }
    for (int idx = tid; idx < 128 * 64; idx += 512) {
        int p = idx >> 6, c = idx & 63;
        ins[p * 67 + xoff + c] = g_lf[(size_t)(base + p) * 64 + c];
    }
    if (!head && tid < 256) {
        int p = tid >> 1, c = tid & 1;
        ins[p * 67 + c] = xg[(size_t)(base + p) * 2 + c];
    }
    __syncthreads();

    if (head) head_body<64>(w1s, b1s, w2s, b2s, ins, hs, outp, base, tid);
    else      head_body<66>(w1s, b1s, w2s, b2s, ins, hs, outp, base, tid);
}

// ---------------- launch ----------------
extern "C" void kernel_launch(void* const* d_in, const int* in_sizes, int n_in,
                              void* d_out, int out_size)
{
    (void)in_sizes; (void)n_in; (void)out_size;
    const float* x   = (const float*)d_in[0];
    const float* lw1 = (const float*)d_in[1];
    const float* lb1 = (const float*)d_in[2];
    const float* lw2 = (const float*)d_in[3];
    const float* lb2 = (const float*)d_in[4];
    const float* lw3 = (const float*)d_in[5];
    const float* lb3 = (const float*)d_in[6];
    const float* cw1 = (const float*)d_in[7];
    const float* cb1 = (const float*)d_in[8];
    const float* cw2 = (const float*)d_in[9];
    const float* cb2 = (const float*)d_in[10];
    const float* tw1 = (const float*)d_in[11];
    const float* tb1 = (const float*)d_in[12];
    const float* tw2 = (const float*)d_in[13];
    const float* tb2 = (const float*)d_in[14];
    float* out = (float*)d_out;

    const int smB = B_SMEM_FLOATS * 4;
    const int smH = H_SMEM_FLOATS * 4;
    cudaFuncSetAttribute(local_mlp_kernel, cudaFuncAttributeMaxDynamicSharedMemorySize, smB);
    cudaFuncSetAttribute(head2_kernel,     cudaFuncAttributeMaxDynamicSharedMemorySize, smH);

    knn_part_kernel<<<dim3(NN/128, SLICES, 8), 128>>>(x);
    knn_merge_geom_kernel<<<NPTS/128, 128>>>(x, out);
    local_mlp_kernel<<<NPTS/32, 512, smB>>>(lw1, lb1, lw2, lb2, lw3, lb3);
    head2_kernel<<<dim3(NPTS/128, 2), 512, smH>>>(x, cw1, cb1, cw2, cb2,
                                                  tw1, tb1, tw2, tb2, out);
}